// round 9
// baseline (speedup 1.0000x reference)
#include <cuda_runtime.h>
#include <cuda_bf16.h>
#include <cstdint>

#define D_      128
#define NVARS   50000
#define V2_     100000
#define NCL     200000
#define NTOTAL  300000
#define NROUNDS 16

// ---------------- persistent scratch ---------------------------------------
__device__ float g_h[(size_t)NTOTAL * D_];
__device__ float g_c[(size_t)NTOTAL * D_];
__device__ float g_msg[(size_t)NCL * D_];
__device__ float g_t0[(size_t)NCL * D_];

// bf16 hi/lo mirrors (u32 = packed bf16x2, 64 u32 per row); h has 2 buffers (ping-pong)
__device__ uint32_t g_hhiA[(size_t)NTOTAL * 64];
__device__ uint32_t g_hloA[(size_t)NTOTAL * 64];
__device__ uint32_t g_hhiB[(size_t)NTOTAL * 64];
__device__ uint32_t g_hloB[(size_t)NTOTAL * 64];
__device__ uint32_t g_mhi[(size_t)NCL * 64];
__device__ uint32_t g_mlo[(size_t)NCL * 64];
__device__ uint32_t g_i1hi[(size_t)NCL * 64];
__device__ uint32_t g_i1lo[(size_t)NCL * 64];
__device__ uint32_t g_i2hi[(size_t)NCL * 64];
__device__ uint32_t g_i2lo[(size_t)NCL * 64];
// weights (u32 chunks): Lmsg(24576) Cmsg(24576) CuWih(32768) CuWhh(32768) LuWih(65536) LuWhh(32768)
#define WO_LMSG  0
#define WO_CMSG  24576
#define WO_CWIH  49152
#define WO_CWHH  81920
#define WO_LWIH  114688
#define WO_LWHH  180224
#define W_TOTAL  212992
__device__ uint32_t g_whi[W_TOTAL];
__device__ uint32_t g_wlo[W_TOTAL];
__device__ float g_pbC[512];
__device__ float g_pbL[512];

// ---------------- helpers ---------------------------------------------------
__device__ __forceinline__ void cvt2(float x, float y, uint32_t& hi, uint32_t& lo) {
    __nv_bfloat16 hx = __float2bfloat16_rn(x);
    __nv_bfloat16 hy = __float2bfloat16_rn(y);
    __nv_bfloat162 hp = __halves2bfloat162(hx, hy);
    hi = *(uint32_t*)&hp;
    __nv_bfloat16 lx = __float2bfloat16_rn(x - __bfloat162float(hx));
    __nv_bfloat16 ly = __float2bfloat16_rn(y - __bfloat162float(hy));
    __nv_bfloat162 lp = __halves2bfloat162(lx, ly);
    lo = *(uint32_t*)&lp;
}

__device__ __forceinline__ void mma_bf16(float* d, const uint32_t* a, uint32_t b0, uint32_t b1) {
    asm volatile(
        "mma.sync.aligned.m16n8k16.row.col.f32.bf16.bf16.f32 "
        "{%0,%1,%2,%3}, {%4,%5,%6,%7}, {%8,%9}, {%0,%1,%2,%3};\n"
        : "+f"(d[0]), "+f"(d[1]), "+f"(d[2]), "+f"(d[3])
        : "r"(a[0]), "r"(a[1]), "r"(a[2]), "r"(a[3]), "r"(b0), "r"(b1));
}

__device__ __forceinline__ uint32_t smem_u32(const void* p) {
    uint32_t a;
    asm("{ .reg .u64 t; cvta.to.shared.u64 t, %1; cvt.u32.u64 %0, t; }" : "=r"(a) : "l"(p));
    return a;
}

__device__ __forceinline__ void cp16(uint32_t saddr, const void* g, bool pred) {
    int sz = pred ? 16 : 0;
    asm volatile("cp.async.cg.shared.global [%0], [%1], 16, %2;"
                 :: "r"(saddr), "l"(g), "r"(sz));
}

__device__ __forceinline__ float sigf(float x) { return 1.f / (1.f + __expf(-x)); }

// gate-interleave permutation: new_row -> old_row
__device__ __forceinline__ int permrow(int nr) {
    int t = nr >> 7, w = nr & 127;
    return (w >> 5) * 128 + t * 32 + (w & 31);
}

// ---------------- GEMM (mma.sync bf16 3-pass, cp.async 2-stage pipeline) ----
#define ASTR 36
#define STAGE_U32 (4 * 128 * ASTR)            // 18432 u32 per stage
#define SMEM_TC_BYTES (2 * STAGE_U32 * 4)     // 147456 B

struct TcArgs {
    const uint32_t *Ahi[3], *Alo[3];
    int negflip[3];
    const uint32_t *Bhi[3], *Blo[3];
    int ldb32[3], bko32[3];
    int nTerms;
    const float *bias0, *bias1;
    float* C;            // fp32 out (optional)
    uint32_t *Chi, *Clo; // bf16 hi/lo out (optional)
    int M, N;
    int relu;
    // fused LSTM (optional)
    int doLstm;
    float *cbuf, *hout;
    uint32_t *houthi, *houtlo;
};

__device__ __forceinline__ void fill_stage(const TcArgs& a, int s, uint32_t sbase,
                                           int brow, int bcol, int tid) {
    const int term = s >> 1, kh = s & 1, b = s & 1;
    const uint32_t st = sbase + (uint32_t)b * (STAGE_U32 * 4);
    const uint32_t* gah = a.Ahi[term];
    const uint32_t* gal = a.Alo[term];
    const int nflip = a.negflip[term];
#pragma unroll
    for (int i = 0; i < 4; ++i) {
        int f = i * 256 + tid;
        int r = f >> 3, cch = f & 7;
        int gr = brow + r;
        bool p = gr < a.M;
        int src = p ? gr : 0;
        if (nflip) src = (src < NVARS) ? src + NVARS : src - NVARS;
        size_t go = (size_t)src * 64 + kh * 32 + cch * 4;
        uint32_t so = st + (uint32_t)(r * ASTR + cch * 4) * 4;
        cp16(so, gah + go, p);
        cp16(so + 4608u * 4, gal + go, p);
    }
    const uint32_t* gbh = a.Bhi[term];
    const uint32_t* gbl = a.Blo[term];
    const int ldb = a.ldb32[term], bko = a.bko32[term];
#pragma unroll
    for (int i = 0; i < 4; ++i) {
        int f = i * 256 + tid;
        int r = f >> 3, cch = f & 7;
        size_t go = (size_t)(bcol + r) * ldb + bko + kh * 32 + cch * 4;
        uint32_t so = st + (uint32_t)(2 * 4608 + r * ASTR + cch * 4) * 4;
        cp16(so, gbh + go, true);
        cp16(so + 4608u * 4, gbl + go, true);
    }
    asm volatile("cp.async.commit_group;" ::: "memory");
}

__global__ __launch_bounds__(256) void tc_gemm(TcArgs a) {
    extern __shared__ uint32_t sm[];
    const uint32_t sbase = smem_u32(sm);
    const int tid  = threadIdx.x;
    const int wid  = tid >> 5;
    const int lane = tid & 31;
    const int g    = lane >> 2;
    const int t    = lane & 3;
    const int wm   = (wid >> 1) * 32;
    const int wn   = (wid & 1) * 64;
    const int brow = blockIdx.x << 7;
    const int bcol = blockIdx.y << 7;

    float acc[2][8][4];
#pragma unroll
    for (int mf = 0; mf < 2; ++mf)
#pragma unroll
        for (int nf = 0; nf < 8; ++nf)
#pragma unroll
            for (int k = 0; k < 4; ++k) acc[mf][nf][k] = 0.f;

    const int nst = a.nTerms * 2;
    fill_stage(a, 0, sbase, brow, bcol, tid);
    fill_stage(a, 1, sbase, brow, bcol, tid);

    for (int s = 0; s < nst; ++s) {
        const int b = s & 1;
        if (s + 1 < nst) asm volatile("cp.async.wait_group 1;" ::: "memory");
        else             asm volatile("cp.async.wait_group 0;" ::: "memory");
        __syncthreads();

        uint32_t* st = sm + b * STAGE_U32;
        uint32_t* SAh = st;
        uint32_t* SAl = st + 4608;
        uint32_t* SBh = st + 2 * 4608;
        uint32_t* SBl = st + 3 * 4608;
#pragma unroll
        for (int ks = 0; ks < 4; ++ks) {
            const int c0 = ks * 8 + t;
            uint32_t ah[2][4], al[2][4];
#pragma unroll
            for (int mf = 0; mf < 2; ++mf) {
                const int r = wm + mf * 16 + g;
                const uint32_t* p = SAh + r * ASTR + c0;
                ah[mf][0] = p[0]; ah[mf][1] = p[8 * ASTR];
                ah[mf][2] = p[4]; ah[mf][3] = p[8 * ASTR + 4];
                const uint32_t* q = SAl + r * ASTR + c0;
                al[mf][0] = q[0]; al[mf][1] = q[8 * ASTR];
                al[mf][2] = q[4]; al[mf][3] = q[8 * ASTR + 4];
            }
#pragma unroll
            for (int nf = 0; nf < 8; ++nf) {
                const int nr = wn + nf * 8 + g;
                const uint32_t* pb = SBh + nr * ASTR + c0;
                uint32_t bh0 = pb[0], bh1 = pb[4];
                const uint32_t* qb = SBl + nr * ASTR + c0;
                uint32_t bl0 = qb[0], bl1 = qb[4];
#pragma unroll
                for (int mf = 0; mf < 2; ++mf) {
                    mma_bf16(acc[mf][nf], ah[mf], bh0, bh1);
                    mma_bf16(acc[mf][nf], ah[mf], bl0, bl1);
                    mma_bf16(acc[mf][nf], al[mf], bh0, bh1);
                }
            }
        }
        __syncthreads();
        if (s + 2 < nst) fill_stage(a, s + 2, sbase, brow, bcol, tid);
    }

    if (!a.doLstm) {
        // ---- plain epilogue: bias (+bias1), opt relu, fp32 and/or hi/lo out ----
#pragma unroll
        for (int nf = 0; nf < 8; ++nf) {
            const int col = bcol + wn + nf * 8 + 2 * t;
            float b0v = a.bias0[col], b1v = a.bias0[col + 1];
            if (a.bias1) { b0v += a.bias1[col]; b1v += a.bias1[col + 1]; }
#pragma unroll
            for (int mf = 0; mf < 2; ++mf) {
                const int row = brow + wm + mf * 16 + g;
                float x0 = acc[mf][nf][0] + b0v;
                float x1 = acc[mf][nf][1] + b1v;
                float x2 = acc[mf][nf][2] + b0v;
                float x3 = acc[mf][nf][3] + b1v;
                if (a.relu) {
                    x0 = fmaxf(x0, 0.f); x1 = fmaxf(x1, 0.f);
                    x2 = fmaxf(x2, 0.f); x3 = fmaxf(x3, 0.f);
                }
                if (a.C) {
                    if (row < a.M)
                        *(float2*)(a.C + (size_t)row * a.N + col) = make_float2(x0, x1);
                    if (row + 8 < a.M)
                        *(float2*)(a.C + (size_t)(row + 8) * a.N + col) = make_float2(x2, x3);
                }
                if (a.Chi) {
                    uint32_t hv, lv;
                    if (row < a.M) {
                        cvt2(x0, x1, hv, lv);
                        a.Chi[(size_t)row * 64 + (col >> 1)] = hv;
                        a.Clo[(size_t)row * 64 + (col >> 1)] = lv;
                    }
                    if (row + 8 < a.M) {
                        cvt2(x2, x3, hv, lv);
                        a.Chi[(size_t)(row + 8) * 64 + (col >> 1)] = hv;
                        a.Clo[(size_t)(row + 8) * 64 + (col >> 1)] = lv;
                    }
                }
            }
        }
        return;
    }

    // ---- fused LSTM epilogue ----
    // stage the 128x128 gate tile (bias added) into smem
    float* tile = (float*)sm;
    const int TST = 132;
#pragma unroll
    for (int nf = 0; nf < 8; ++nf) {
        const int col = wn + nf * 8 + 2 * t;
        const int gcol = bcol + col;
        float b0v = a.bias0[gcol], b1v = a.bias0[gcol + 1];
#pragma unroll
        for (int mf = 0; mf < 2; ++mf) {
            const int r0 = wm + mf * 16 + g;
            tile[r0 * TST + col]     = acc[mf][nf][0] + b0v;
            tile[r0 * TST + col + 1] = acc[mf][nf][1] + b1v;
            tile[(r0 + 8) * TST + col]     = acc[mf][nf][2] + b0v;
            tile[(r0 + 8) * TST + col + 1] = acc[mf][nf][3] + b1v;
        }
    }
    __syncthreads();

    const int fbase = bcol >> 2;   // (bcol/128)*32
#pragma unroll
    for (int i = 0; i < 8; ++i) {
        int idx = i * 256 + tid;       // 0..2047
        int row = idx >> 4;            // 0..127
        int fp  = idx & 15;            // feature pair 0..15
        int grow = brow + row;
        if (grow < a.M) {
            const float* tr = tile + row * TST;
            float i0 = tr[2 * fp],       i1 = tr[2 * fp + 1];
            float f0 = tr[32 + 2 * fp],  f1 = tr[32 + 2 * fp + 1];
            float g0 = tr[64 + 2 * fp],  g1 = tr[64 + 2 * fp + 1];
            float o0 = tr[96 + 2 * fp],  o1 = tr[96 + 2 * fp + 1];
            int fc = fbase + 2 * fp;
            float2 cc = *(float2*)(a.cbuf + (size_t)grow * D_ + fc);
            float c2x = sigf(f0) * cc.x + sigf(i0) * tanhf(g0);
            float c2y = sigf(f1) * cc.y + sigf(i1) * tanhf(g1);
            float hx = sigf(o0) * tanhf(c2x);
            float hy = sigf(o1) * tanhf(c2y);
            *(float2*)(a.cbuf + (size_t)grow * D_ + fc) = make_float2(c2x, c2y);
            *(float2*)(a.hout + (size_t)grow * D_ + fc) = make_float2(hx, hy);
            uint32_t hv, lv;
            cvt2(hx, hy, hv, lv);
            a.houthi[(size_t)grow * 64 + (fc >> 1)] = hv;
            a.houtlo[(size_t)grow * 64 + (fc >> 1)] = lv;
        }
    }
}

// ---------------- edge scatter-add -----------------------------------------
__global__ void scatter_kernel(const float* __restrict__ rows,
                               const int* __restrict__ gidx,
                               const int* __restrict__ sidx,
                               int E, float* __restrict__ out) {
    int e = blockIdx.x * 8 + threadIdx.y;
    if (e >= E) return;
    int s = gidx[e];
    int d = sidx[e];
    float4 v = *(const float4*)(rows + (size_t)s * D_ + threadIdx.x * 4);
    float* p = out + (size_t)d * D_ + threadIdx.x * 4;
    asm volatile("red.global.add.v4.f32 [%0], {%1, %2, %3, %4};"
                 :: "l"(p), "f"(v.x), "f"(v.y), "f"(v.z), "f"(v.w)
                 : "memory");
}

// ---------------- small kernels --------------------------------------------
__global__ void init_kernel(const float* __restrict__ lw, const float* __restrict__ lb,
                            const float* __restrict__ cw, const float* __restrict__ cb,
                            float* __restrict__ h,
                            uint32_t* __restrict__ hhi, uint32_t* __restrict__ hlo) {
    int tid = threadIdx.x;           // 0..63
    size_t row = blockIdx.x;
    int d0 = tid * 2;
    float v0, v1;
    if (row < V2_) { v0 = lw[d0] + lb[d0]; v1 = lw[d0 + 1] + lb[d0 + 1]; }
    else           { v0 = cw[d0] + cb[d0]; v1 = cw[d0 + 1] + cb[d0 + 1]; }
    h[row * D_ + d0] = v0;
    h[row * D_ + d0 + 1] = v1;
    uint32_t hv, lv;
    cvt2(v0, v1, hv, lv);
    hhi[row * 64 + tid] = hv;
    hlo[row * 64 + tid] = lv;
}

__global__ void cvt_pairs(const float2* __restrict__ src,
                          uint32_t* __restrict__ hi, uint32_t* __restrict__ lo, size_t n) {
    size_t i = (size_t)blockIdx.x * blockDim.x + threadIdx.x;
    if (i >= n) return;
    float2 v = src[i];
    uint32_t hv, lv;
    cvt2(v.x, v.y, hv, lv);
    hi[i] = hv; lo[i] = lv;
}

__global__ void cvt_perm(const float2* __restrict__ src,
                         uint32_t* __restrict__ hi, uint32_t* __restrict__ lo, int ld32) {
    int i = blockIdx.x * 256 + threadIdx.x;
    int n = 512 * ld32;
    if (i >= n) return;
    int nr = i / ld32, c = i % ld32;
    int old = permrow(nr);
    float2 v = src[(size_t)old * ld32 + c];
    uint32_t hv, lv;
    cvt2(v.x, v.y, hv, lv);
    hi[i] = hv; lo[i] = lv;
}

__global__ void perm_bias(const float* __restrict__ b0, const float* __restrict__ b1,
                          float* __restrict__ out) {
    int nr = blockIdx.x * 256 + threadIdx.x;
    if (nr >= 512) return;
    int old = permrow(nr);
    out[nr] = b0[old] + b1[old];
}

__global__ void zero_kernel(float4* __restrict__ p, size_t n4) {
    size_t i = (size_t)blockIdx.x * blockDim.x + threadIdx.x;
    if (i < n4) p[i] = make_float4(0.f, 0.f, 0.f, 0.f);
}

__global__ void copy_kernel(const float4* __restrict__ src, float4* __restrict__ dst, size_t n4) {
    size_t i = (size_t)blockIdx.x * blockDim.x + threadIdx.x;
    if (i < n4) dst[i] = src[i];
}

// ---------------- host wrappers --------------------------------------------
static void tc_launch(TcArgs& a) {
    dim3 grid((a.M + 127) >> 7, a.N >> 7);
    tc_gemm<<<grid, 256, SMEM_TC_BYTES>>>(a);
}

extern "C" void kernel_launch(void* const* d_in, const int* in_sizes, int n_in,
                              void* d_out, int out_size) {
    const float* L_init_w = (const float*)d_in[0];
    const float* L_init_b = (const float*)d_in[1];
    const float* C_init_w = (const float*)d_in[2];
    const float* C_init_b = (const float*)d_in[3];
    const float* Lmsg_w   = (const float*)d_in[4];
    const float* Lmsg_b   = (const float*)d_in[5];
    const float* Cmsg_w   = (const float*)d_in[6];
    const float* Cmsg_b   = (const float*)d_in[7];
    const float* Cu_wih   = (const float*)d_in[8];
    const float* Cu_whh   = (const float*)d_in[9];
    const float* Cu_bih   = (const float*)d_in[10];
    const float* Cu_bhh   = (const float*)d_in[11];
    const float* Lu_wih   = (const float*)d_in[12];
    const float* Lu_whh   = (const float*)d_in[13];
    const float* Lu_bih   = (const float*)d_in[14];
    const float* Lu_bhh   = (const float*)d_in[15];
    const int*   esrc     = (const int*)d_in[16];
    const int*   edst     = (const int*)d_in[17];
    const int E = in_sizes[16];

    static int smem_set = 0;
    if (!smem_set) {
        cudaFuncSetAttribute(tc_gemm, cudaFuncAttributeMaxDynamicSharedMemorySize, SMEM_TC_BYTES);
        smem_set = 1;
    }

    float *h, *c, *msg, *t0, *pbC, *pbL;
    uint32_t *hhiA, *hloA, *hhiB, *hloB, *mhi, *mlo, *i1hi, *i1lo, *i2hi, *i2lo, *whi, *wlo;
    cudaGetSymbolAddress((void**)&h,     g_h);
    cudaGetSymbolAddress((void**)&c,     g_c);
    cudaGetSymbolAddress((void**)&msg,   g_msg);
    cudaGetSymbolAddress((void**)&t0,    g_t0);
    cudaGetSymbolAddress((void**)&hhiA,  g_hhiA);
    cudaGetSymbolAddress((void**)&hloA,  g_hloA);
    cudaGetSymbolAddress((void**)&hhiB,  g_hhiB);
    cudaGetSymbolAddress((void**)&hloB,  g_hloB);
    cudaGetSymbolAddress((void**)&mhi,   g_mhi);
    cudaGetSymbolAddress((void**)&mlo,   g_mlo);
    cudaGetSymbolAddress((void**)&i1hi,  g_i1hi);
    cudaGetSymbolAddress((void**)&i1lo,  g_i1lo);
    cudaGetSymbolAddress((void**)&i2hi,  g_i2hi);
    cudaGetSymbolAddress((void**)&i2lo,  g_i2lo);
    cudaGetSymbolAddress((void**)&whi,   g_whi);
    cudaGetSymbolAddress((void**)&wlo,   g_wlo);
    cudaGetSymbolAddress((void**)&pbC,   g_pbC);
    cudaGetSymbolAddress((void**)&pbL,   g_pbL);

    // ---- pre-convert weights; gate matrices get row-permuted ----
    cvt_pairs<<<(24576 + 255) / 256, 256>>>((const float2*)Lmsg_w, whi + WO_LMSG, wlo + WO_LMSG, 24576);
    cvt_pairs<<<(24576 + 255) / 256, 256>>>((const float2*)Cmsg_w, whi + WO_CMSG, wlo + WO_CMSG, 24576);
    cvt_perm<<<128, 256>>>((const float2*)Cu_wih, whi + WO_CWIH, wlo + WO_CWIH, 64);
    cvt_perm<<<128, 256>>>((const float2*)Cu_whh, whi + WO_CWHH, wlo + WO_CWHH, 64);
    cvt_perm<<<256, 256>>>((const float2*)Lu_wih, whi + WO_LWIH, wlo + WO_LWIH, 128);
    cvt_perm<<<128, 256>>>((const float2*)Lu_whh, whi + WO_LWHH, wlo + WO_LWHH, 64);
    perm_bias<<<2, 256>>>(Cu_bih, Cu_bhh, pbC);
    perm_bias<<<2, 256>>>(Lu_bih, Lu_bhh, pbL);

    init_kernel<<<NTOTAL, 64>>>(L_init_w, L_init_b, C_init_w, C_init_b, h, hhiA, hloA);
    zero_kernel<<<((size_t)NTOTAL * 32 + 255) / 256, 256>>>((float4*)c, (size_t)NTOTAL * 32);

    dim3 sblk(32, 8);
    int sgrid = (E + 7) / 8;

    uint32_t *curhi = hhiA, *curlo = hloA, *nxthi = hhiB, *nxtlo = hloB;

    for (int r = 0; r < NROUNDS; ++r) {
        TcArgs a;

        // ---- L-MLP layer 1: h(lit) -> i1 ----
        a = {};
        a.Ahi[0] = curhi; a.Alo[0] = curlo;
        a.Bhi[0] = whi + WO_LMSG; a.Blo[0] = wlo + WO_LMSG; a.ldb32[0] = 64;
        a.nTerms = 1; a.bias0 = Lmsg_b; a.Chi = i1hi; a.Clo = i1lo;
        a.M = V2_; a.N = 128; a.relu = 1;
        tc_launch(a);
        // layer 2
        a.Ahi[0] = i1hi; a.Alo[0] = i1lo;
        a.Bhi[0] = whi + WO_LMSG + 8192; a.Blo[0] = wlo + WO_LMSG + 8192;
        a.bias0 = Lmsg_b + 128; a.Chi = i2hi; a.Clo = i2lo;
        tc_launch(a);
        // layer 3 -> t0 fp32
        a.Ahi[0] = i2hi; a.Alo[0] = i2lo;
        a.Bhi[0] = whi + WO_LMSG + 16384; a.Blo[0] = wlo + WO_LMSG + 16384;
        a.bias0 = Lmsg_b + 256; a.Chi = nullptr; a.Clo = nullptr;
        a.C = t0; a.relu = 0;
        tc_launch(a);

        zero_kernel<<<((size_t)NCL * 32 + 255) / 256, 256>>>((float4*)msg, (size_t)NCL * 32);
        scatter_kernel<<<sgrid, sblk>>>(t0, esrc, edst, E, msg);
        cvt_pairs<<<((size_t)NCL * 64 + 255) / 256, 256>>>((const float2*)msg, mhi, mlo, (size_t)NCL * 64);

        // ---- clause gates + fused LSTM ----
        a = {};
        a.Ahi[0] = mhi; a.Alo[0] = mlo;
        a.Bhi[0] = whi + WO_CWIH; a.Blo[0] = wlo + WO_CWIH; a.ldb32[0] = 64;
        a.Ahi[1] = curhi + (size_t)V2_ * 64; a.Alo[1] = curlo + (size_t)V2_ * 64;
        a.Bhi[1] = whi + WO_CWHH; a.Blo[1] = wlo + WO_CWHH; a.ldb32[1] = 64;
        a.nTerms = 2; a.bias0 = pbC;
        a.M = NCL; a.N = 512;
        a.doLstm = 1;
        a.cbuf = c + (size_t)V2_ * D_;
        a.hout = h + (size_t)V2_ * D_;
        a.houthi = nxthi + (size_t)V2_ * 64;
        a.houtlo = nxtlo + (size_t)V2_ * 64;
        tc_launch(a);

        // ---- C-MLP (reads NEW clause h from nxt) ----
        a = {};
        a.Ahi[0] = nxthi + (size_t)V2_ * 64; a.Alo[0] = nxtlo + (size_t)V2_ * 64;
        a.Bhi[0] = whi + WO_CMSG; a.Blo[0] = wlo + WO_CMSG; a.ldb32[0] = 64;
        a.nTerms = 1; a.bias0 = Cmsg_b; a.Chi = i1hi; a.Clo = i1lo;
        a.M = NCL; a.N = 128; a.relu = 1;
        tc_launch(a);
        a.Ahi[0] = i1hi; a.Alo[0] = i1lo;
        a.Bhi[0] = whi + WO_CMSG + 8192; a.Blo[0] = wlo + WO_CMSG + 8192;
        a.bias0 = Cmsg_b + 128; a.Chi = i2hi; a.Clo = i2lo;
        tc_launch(a);
        a.Ahi[0] = i2hi; a.Alo[0] = i2lo;
        a.Bhi[0] = whi + WO_CMSG + 16384; a.Blo[0] = wlo + WO_CMSG + 16384;
        a.bias0 = Cmsg_b + 256; a.Chi = nullptr; a.Clo = nullptr;
        a.C = t0; a.relu = 0;
        tc_launch(a);

        zero_kernel<<<((size_t)V2_ * 32 + 255) / 256, 256>>>((float4*)msg, (size_t)V2_ * 32);
        scatter_kernel<<<sgrid, sblk>>>(t0, edst, esrc, E, msg);
        cvt_pairs<<<((size_t)V2_ * 64 + 255) / 256, 256>>>((const float2*)msg, mhi, mlo, (size_t)V2_ * 64);

        // ---- literal gates + fused LSTM ----
        a = {};
        a.Ahi[0] = mhi; a.Alo[0] = mlo;
        a.Bhi[0] = whi + WO_LWIH; a.Blo[0] = wlo + WO_LWIH; a.ldb32[0] = 128; a.bko32[0] = 0;
        a.Ahi[1] = curhi; a.Alo[1] = curlo; a.negflip[1] = 1;
        a.Bhi[1] = whi + WO_LWIH; a.Blo[1] = wlo + WO_LWIH; a.ldb32[1] = 128; a.bko32[1] = 64;
        a.Ahi[2] = curhi; a.Alo[2] = curlo;
        a.Bhi[2] = whi + WO_LWHH; a.Blo[2] = wlo + WO_LWHH; a.ldb32[2] = 64;
        a.nTerms = 3; a.bias0 = pbL;
        a.M = V2_; a.N = 512;
        a.doLstm = 1;
        a.cbuf = c; a.hout = h;
        a.houthi = nxthi; a.houtlo = nxtlo;
        tc_launch(a);

        // swap ping-pong
        uint32_t* th = curhi; curhi = nxthi; nxthi = th;
        uint32_t* tl = curlo; curlo = nxtlo; nxtlo = tl;
    }

    copy_kernel<<<((size_t)NTOTAL * 32 + 255) / 256, 256>>>(
        (const float4*)h, (float4*)d_out, (size_t)NTOTAL * 32);
}

// round 11
// speedup vs baseline: 1.0817x; 1.0817x over previous
#include <cuda_runtime.h>
#include <cuda_bf16.h>
#include <cstdint>

#define D_      128
#define NVARS   50000
#define V2_     100000
#define NCL     200000
#define NTOTAL  300000
#define NROUNDS 16

// ---------------- persistent scratch ---------------------------------------
__device__ float g_h[(size_t)NTOTAL * D_];
__device__ float g_c[(size_t)NTOTAL * D_];
__device__ float g_msg[(size_t)NCL * D_];
__device__ float g_t0[(size_t)NCL * D_];
__device__ float g_gates[(size_t)NCL * 4 * D_];

// bf16 hi/lo mirrors (u32 = packed bf16x2, 64 u32 per 128-float row)
__device__ uint32_t g_hhi[(size_t)NTOTAL * 64];
__device__ uint32_t g_hlo[(size_t)NTOTAL * 64];
__device__ uint32_t g_mhi[(size_t)NCL * 64];
__device__ uint32_t g_mlo[(size_t)NCL * 64];
__device__ uint32_t g_i1hi[(size_t)NCL * 64];
__device__ uint32_t g_i1lo[(size_t)NCL * 64];
__device__ uint32_t g_i2hi[(size_t)NCL * 64];
__device__ uint32_t g_i2lo[(size_t)NCL * 64];
// weights: Lmsg(24576) Cmsg(24576) CuWih(32768) CuWhh(32768) LuWih(65536) LuWhh(32768)
#define WO_LMSG  0
#define WO_CMSG  24576
#define WO_CWIH  49152
#define WO_CWHH  81920
#define WO_LWIH  114688
#define WO_LWHH  180224
#define W_TOTAL  212992
__device__ uint32_t g_whi[W_TOTAL];
__device__ uint32_t g_wlo[W_TOTAL];

// ---------------- helpers ---------------------------------------------------
__device__ __forceinline__ void cvt2(float x, float y, uint32_t& hi, uint32_t& lo) {
    __nv_bfloat16 hx = __float2bfloat16_rn(x);
    __nv_bfloat16 hy = __float2bfloat16_rn(y);
    __nv_bfloat162 hp = __halves2bfloat162(hx, hy);
    hi = *(uint32_t*)&hp;
    __nv_bfloat16 lx = __float2bfloat16_rn(x - __bfloat162float(hx));
    __nv_bfloat16 ly = __float2bfloat16_rn(y - __bfloat162float(hy));
    __nv_bfloat162 lp = __halves2bfloat162(lx, ly);
    lo = *(uint32_t*)&lp;
}

__device__ __forceinline__ void mma_bf16(float* d, const uint32_t* a, uint32_t b0, uint32_t b1) {
    asm volatile(
        "mma.sync.aligned.m16n8k16.row.col.f32.bf16.bf16.f32 "
        "{%0,%1,%2,%3}, {%4,%5,%6,%7}, {%8,%9}, {%0,%1,%2,%3};\n"
        : "+f"(d[0]), "+f"(d[1]), "+f"(d[2]), "+f"(d[3])
        : "r"(a[0]), "r"(a[1]), "r"(a[2]), "r"(a[3]), "r"(b0), "r"(b1));
}

__device__ __forceinline__ uint32_t smem_u32(const void* p) {
    uint32_t a;
    asm("{ .reg .u64 t; cvta.to.shared.u64 t, %1; cvt.u32.u64 %0, t; }" : "=r"(a) : "l"(p));
    return a;
}

__device__ __forceinline__ void cp16(uint32_t saddr, const void* g, bool pred) {
    int sz = pred ? 16 : 0;
    asm volatile("cp.async.cg.shared.global [%0], [%1], 16, %2;"
                 :: "r"(saddr), "l"(g), "r"(sz));
}

// ---------------- GEMM (mma.sync bf16 3-pass, cp.async 2-stage, 16 warps) ---
#define ASTR 36
#define STAGE_U32 (4 * 128 * ASTR)            // 18432 u32 per stage
#define SMEM_TC_BYTES (2 * STAGE_U32 * 4)     // 147456 B

struct TcArgs {
    const uint32_t *Ahi[3], *Alo[3];
    int negflip[3];
    const uint32_t *Bhi[3], *Blo[3];
    int ldb32[3], bko32[3];
    int nTerms;
    const float *bias0, *bias1;
    float* C;            // fp32 out (optional)
    uint32_t *Chi, *Clo; // bf16 hi/lo out (optional)
    int M, N;
    int relu;
};

__device__ __forceinline__ void fill_stage(const TcArgs& a, int s, uint32_t sbase,
                                           int brow, int bcol, int tid) {
    const int term = s >> 1, kh = s & 1, b = s & 1;
    const uint32_t st = sbase + (uint32_t)b * (STAGE_U32 * 4);
    const uint32_t* gah = a.Ahi[term];
    const uint32_t* gal = a.Alo[term];
    const int nflip = a.negflip[term];
#pragma unroll
    for (int i = 0; i < 2; ++i) {
        int f = i * 512 + tid;
        int r = f >> 3, cch = f & 7;
        int gr = brow + r;
        bool p = gr < a.M;
        int src = p ? gr : 0;
        if (nflip) src = (src < NVARS) ? src + NVARS : src - NVARS;
        size_t go = (size_t)src * 64 + kh * 32 + cch * 4;
        uint32_t so = st + (uint32_t)(r * ASTR + cch * 4) * 4;
        cp16(so, gah + go, p);
        cp16(so + 4608u * 4, gal + go, p);
    }
    const uint32_t* gbh = a.Bhi[term];
    const uint32_t* gbl = a.Blo[term];
    const int ldb = a.ldb32[term], bko = a.bko32[term];
#pragma unroll
    for (int i = 0; i < 2; ++i) {
        int f = i * 512 + tid;
        int r = f >> 3, cch = f & 7;
        size_t go = (size_t)(bcol + r) * ldb + bko + kh * 32 + cch * 4;
        uint32_t so = st + (uint32_t)(2 * 4608 + r * ASTR + cch * 4) * 4;
        cp16(so, gbh + go, true);
        cp16(so + 4608u * 4, gbl + go, true);
    }
    asm volatile("cp.async.commit_group;" ::: "memory");
}

__global__ __launch_bounds__(512) void tc_gemm(TcArgs a) {
    extern __shared__ uint32_t sm[];
    const uint32_t sbase = smem_u32(sm);
    const int tid  = threadIdx.x;
    const int wid  = tid >> 5;         // 0..15
    const int lane = tid & 31;
    const int g    = lane >> 2;
    const int t    = lane & 3;
    const int wm   = (wid >> 2) * 32;  // 4 warp-rows of 32
    const int wn   = (wid & 3) * 32;   // 4 warp-cols of 32
    const int brow = blockIdx.x << 7;
    const int bcol = blockIdx.y << 7;

    float acc[2][4][4];
#pragma unroll
    for (int mf = 0; mf < 2; ++mf)
#pragma unroll
        for (int nf = 0; nf < 4; ++nf)
#pragma unroll
            for (int k = 0; k < 4; ++k) acc[mf][nf][k] = 0.f;

    const int nst = a.nTerms * 2;
    fill_stage(a, 0, sbase, brow, bcol, tid);
    fill_stage(a, 1, sbase, brow, bcol, tid);

    for (int s = 0; s < nst; ++s) {
        const int b = s & 1;
        if (s + 1 < nst) asm volatile("cp.async.wait_group 1;" ::: "memory");
        else             asm volatile("cp.async.wait_group 0;" ::: "memory");
        __syncthreads();

        uint32_t* st = sm + b * STAGE_U32;
        uint32_t* SAh = st;
        uint32_t* SAl = st + 4608;
        uint32_t* SBh = st + 2 * 4608;
        uint32_t* SBl = st + 3 * 4608;
#pragma unroll
        for (int ks = 0; ks < 4; ++ks) {
            const int c0 = ks * 8 + t;
            uint32_t ah[2][4], al[2][4];
#pragma unroll
            for (int mf = 0; mf < 2; ++mf) {
                const int r = wm + mf * 16 + g;
                const uint32_t* p = SAh + r * ASTR + c0;
                ah[mf][0] = p[0]; ah[mf][1] = p[8 * ASTR];
                ah[mf][2] = p[4]; ah[mf][3] = p[8 * ASTR + 4];
                const uint32_t* q = SAl + r * ASTR + c0;
                al[mf][0] = q[0]; al[mf][1] = q[8 * ASTR];
                al[mf][2] = q[4]; al[mf][3] = q[8 * ASTR + 4];
            }
#pragma unroll
            for (int nf = 0; nf < 4; ++nf) {
                const int nr = wn + nf * 8 + g;
                const uint32_t* pb = SBh + nr * ASTR + c0;
                uint32_t bh0 = pb[0], bh1 = pb[4];
                const uint32_t* qb = SBl + nr * ASTR + c0;
                uint32_t bl0 = qb[0], bl1 = qb[4];
#pragma unroll
                for (int mf = 0; mf < 2; ++mf) {
                    mma_bf16(acc[mf][nf], ah[mf], bh0, bh1);
                    mma_bf16(acc[mf][nf], ah[mf], bl0, bl1);
                    mma_bf16(acc[mf][nf], al[mf], bh0, bh1);
                }
            }
        }
        __syncthreads();
        if (s + 2 < nst) fill_stage(a, s + 2, sbase, brow, bcol, tid);
    }

    // ---- epilogue: bias (+bias1), opt relu, fp32 and/or hi/lo out ----
#pragma unroll
    for (int nf = 0; nf < 4; ++nf) {
        const int col = bcol + wn + nf * 8 + 2 * t;
        float b0v = a.bias0[col], b1v = a.bias0[col + 1];
        if (a.bias1) { b0v += a.bias1[col]; b1v += a.bias1[col + 1]; }
#pragma unroll
        for (int mf = 0; mf < 2; ++mf) {
            const int row = brow + wm + mf * 16 + g;
            float x0 = acc[mf][nf][0] + b0v;
            float x1 = acc[mf][nf][1] + b1v;
            float x2 = acc[mf][nf][2] + b0v;
            float x3 = acc[mf][nf][3] + b1v;
            if (a.relu) {
                x0 = fmaxf(x0, 0.f); x1 = fmaxf(x1, 0.f);
                x2 = fmaxf(x2, 0.f); x3 = fmaxf(x3, 0.f);
            }
            if (a.C) {
                if (row < a.M)
                    *(float2*)(a.C + (size_t)row * a.N + col) = make_float2(x0, x1);
                if (row + 8 < a.M)
                    *(float2*)(a.C + (size_t)(row + 8) * a.N + col) = make_float2(x2, x3);
            }
            if (a.Chi) {
                uint32_t hv, lv;
                if (row < a.M) {
                    cvt2(x0, x1, hv, lv);
                    a.Chi[(size_t)row * 64 + (col >> 1)] = hv;
                    a.Clo[(size_t)row * 64 + (col >> 1)] = lv;
                }
                if (row + 8 < a.M) {
                    cvt2(x2, x3, hv, lv);
                    a.Chi[(size_t)(row + 8) * 64 + (col >> 1)] = hv;
                    a.Clo[(size_t)(row + 8) * 64 + (col >> 1)] = lv;
                }
            }
        }
    }
}

// ---------------- edge scatter-add -----------------------------------------
__global__ void scatter_kernel(const float* __restrict__ rows,
                               const int* __restrict__ gidx,
                               const int* __restrict__ sidx,
                               int E, float* __restrict__ out) {
    int e = blockIdx.x * 8 + threadIdx.y;
    if (e >= E) return;
    int s = gidx[e];
    int d = sidx[e];
    float4 v = *(const float4*)(rows + (size_t)s * D_ + threadIdx.x * 4);
    float* p = out + (size_t)d * D_ + threadIdx.x * 4;
    asm volatile("red.global.add.v4.f32 [%0], {%1, %2, %3, %4};"
                 :: "l"(p), "f"(v.x), "f"(v.y), "f"(v.z), "f"(v.w)
                 : "memory");
}

// ---------------- elementwise ----------------------------------------------
__device__ __forceinline__ float sigf(float x) {
    return __fdividef(1.f, 1.f + __expf(-x));
}
__device__ __forceinline__ float tanhfast(float x) {
    return __fdividef(2.f, 1.f + __expf(-2.f * x)) - 1.f;
}

__global__ void lstm_kernel(const float* __restrict__ gates,
                            float* __restrict__ h, float* __restrict__ c,
                            uint32_t* __restrict__ hhi, uint32_t* __restrict__ hlo,
                            int M) {
    size_t idx = (size_t)blockIdx.x * blockDim.x + threadIdx.x;
    if (idx >= (size_t)M * 32) return;
    size_t r = idx >> 5;
    int q = (int)(idx & 31) * 4;
    const float* gb = gates + r * 512;
    float4 gi = *(const float4*)(gb + q);
    float4 gf = *(const float4*)(gb + 128 + q);
    float4 gg = *(const float4*)(gb + 256 + q);
    float4 go = *(const float4*)(gb + 384 + q);
    float4 cc = *(const float4*)(c + r * D_ + q);
    float4 c2, hh;
    c2.x = sigf(gf.x) * cc.x + sigf(gi.x) * tanhfast(gg.x); hh.x = sigf(go.x) * tanhfast(c2.x);
    c2.y = sigf(gf.y) * cc.y + sigf(gi.y) * tanhfast(gg.y); hh.y = sigf(go.y) * tanhfast(c2.y);
    c2.z = sigf(gf.z) * cc.z + sigf(gi.z) * tanhfast(gg.z); hh.z = sigf(go.z) * tanhfast(c2.z);
    c2.w = sigf(gf.w) * cc.w + sigf(gi.w) * tanhfast(gg.w); hh.w = sigf(go.w) * tanhfast(c2.w);
    *(float4*)(c + r * D_ + q) = c2;
    *(float4*)(h + r * D_ + q) = hh;
    uint32_t h0, l0, h1, l1;
    cvt2(hh.x, hh.y, h0, l0);
    cvt2(hh.z, hh.w, h1, l1);
    *(uint2*)(hhi + r * 64 + (q >> 1)) = make_uint2(h0, h1);
    *(uint2*)(hlo + r * 64 + (q >> 1)) = make_uint2(l0, l1);
}

__global__ void init_kernel(const float* __restrict__ lw, const float* __restrict__ lb,
                            const float* __restrict__ cw, const float* __restrict__ cb,
                            float* __restrict__ h,
                            uint32_t* __restrict__ hhi, uint32_t* __restrict__ hlo) {
    int tid = threadIdx.x;           // 0..63
    size_t row = blockIdx.x;
    int d0 = tid * 2;
    float v0, v1;
    if (row < V2_) { v0 = lw[d0] + lb[d0]; v1 = lw[d0 + 1] + lb[d0 + 1]; }
    else           { v0 = cw[d0] + cb[d0]; v1 = cw[d0 + 1] + cb[d0 + 1]; }
    h[row * D_ + d0] = v0;
    h[row * D_ + d0 + 1] = v1;
    uint32_t hv, lv;
    cvt2(v0, v1, hv, lv);
    hhi[row * 64 + tid] = hv;
    hlo[row * 64 + tid] = lv;
}

__global__ void cvt_pairs(const float2* __restrict__ src,
                          uint32_t* __restrict__ hi, uint32_t* __restrict__ lo, size_t n) {
    size_t i = (size_t)blockIdx.x * blockDim.x + threadIdx.x;
    if (i >= n) return;
    float2 v = src[i];
    uint32_t hv, lv;
    cvt2(v.x, v.y, hv, lv);
    hi[i] = hv; lo[i] = lv;
}

__global__ void zero_kernel(float4* __restrict__ p, size_t n4) {
    size_t i = (size_t)blockIdx.x * blockDim.x + threadIdx.x;
    if (i < n4) p[i] = make_float4(0.f, 0.f, 0.f, 0.f);
}

__global__ void copy_kernel(const float4* __restrict__ src, float4* __restrict__ dst, size_t n4) {
    size_t i = (size_t)blockIdx.x * blockDim.x + threadIdx.x;
    if (i < n4) dst[i] = src[i];
}

// ---------------- host wrappers --------------------------------------------
static void tc_launch(TcArgs& a) {
    dim3 grid((a.M + 127) >> 7, a.N >> 7);
    tc_gemm<<<grid, 512, SMEM_TC_BYTES>>>(a);
}

extern "C" void kernel_launch(void* const* d_in, const int* in_sizes, int n_in,
                              void* d_out, int out_size) {
    const float* L_init_w = (const float*)d_in[0];
    const float* L_init_b = (const float*)d_in[1];
    const float* C_init_w = (const float*)d_in[2];
    const float* C_init_b = (const float*)d_in[3];
    const float* Lmsg_w   = (const float*)d_in[4];
    const float* Lmsg_b   = (const float*)d_in[5];
    const float* Cmsg_w   = (const float*)d_in[6];
    const float* Cmsg_b   = (const float*)d_in[7];
    const float* Cu_wih   = (const float*)d_in[8];
    const float* Cu_whh   = (const float*)d_in[9];
    const float* Cu_bih   = (const float*)d_in[10];
    const float* Cu_bhh   = (const float*)d_in[11];
    const float* Lu_wih   = (const float*)d_in[12];
    const float* Lu_whh   = (const float*)d_in[13];
    const float* Lu_bih   = (const float*)d_in[14];
    const float* Lu_bhh   = (const float*)d_in[15];
    const int*   esrc     = (const int*)d_in[16];
    const int*   edst     = (const int*)d_in[17];
    const int E = in_sizes[16];

    static int smem_set = 0;
    if (!smem_set) {
        cudaFuncSetAttribute(tc_gemm, cudaFuncAttributeMaxDynamicSharedMemorySize, SMEM_TC_BYTES);
        smem_set = 1;
    }

    float *h, *c, *msg, *t0, *gates;
    uint32_t *hhi, *hlo, *mhi, *mlo, *i1hi, *i1lo, *i2hi, *i2lo, *whi, *wlo;
    cudaGetSymbolAddress((void**)&h,     g_h);
    cudaGetSymbolAddress((void**)&c,     g_c);
    cudaGetSymbolAddress((void**)&msg,   g_msg);
    cudaGetSymbolAddress((void**)&t0,    g_t0);
    cudaGetSymbolAddress((void**)&gates, g_gates);
    cudaGetSymbolAddress((void**)&hhi,   g_hhi);
    cudaGetSymbolAddress((void**)&hlo,   g_hlo);
    cudaGetSymbolAddress((void**)&mhi,   g_mhi);
    cudaGetSymbolAddress((void**)&mlo,   g_mlo);
    cudaGetSymbolAddress((void**)&i1hi,  g_i1hi);
    cudaGetSymbolAddress((void**)&i1lo,  g_i1lo);
    cudaGetSymbolAddress((void**)&i2hi,  g_i2hi);
    cudaGetSymbolAddress((void**)&i2lo,  g_i2lo);
    cudaGetSymbolAddress((void**)&whi,   g_whi);
    cudaGetSymbolAddress((void**)&wlo,   g_wlo);

    // ---- pre-convert weights (cheap, once per launch) ----
    cvt_pairs<<<(24576 + 255) / 256, 256>>>((const float2*)Lmsg_w, whi + WO_LMSG, wlo + WO_LMSG, 24576);
    cvt_pairs<<<(24576 + 255) / 256, 256>>>((const float2*)Cmsg_w, whi + WO_CMSG, wlo + WO_CMSG, 24576);
    cvt_pairs<<<(32768 + 255) / 256, 256>>>((const float2*)Cu_wih, whi + WO_CWIH, wlo + WO_CWIH, 32768);
    cvt_pairs<<<(32768 + 255) / 256, 256>>>((const float2*)Cu_whh, whi + WO_CWHH, wlo + WO_CWHH, 32768);
    cvt_pairs<<<(65536 + 255) / 256, 256>>>((const float2*)Lu_wih, whi + WO_LWIH, wlo + WO_LWIH, 65536);
    cvt_pairs<<<(32768 + 255) / 256, 256>>>((const float2*)Lu_whh, whi + WO_LWHH, wlo + WO_LWHH, 32768);

    init_kernel<<<NTOTAL, 64>>>(L_init_w, L_init_b, C_init_w, C_init_b, h, hhi, hlo);
    zero_kernel<<<((size_t)NTOTAL * 32 + 255) / 256, 256>>>((float4*)c, (size_t)NTOTAL * 32);

    dim3 sblk(32, 8);
    int sgrid = (E + 7) / 8;

    for (int r = 0; r < NROUNDS; ++r) {
        TcArgs a;

        // ---- L-MLP layer 1: A=h(lit) -> i1 (hi/lo only) ----
        a = {};
        a.Ahi[0] = hhi; a.Alo[0] = hlo;
        a.Bhi[0] = whi + WO_LMSG; a.Blo[0] = wlo + WO_LMSG; a.ldb32[0] = 64;
        a.nTerms = 1; a.bias0 = Lmsg_b; a.Chi = i1hi; a.Clo = i1lo;
        a.M = V2_; a.N = 128; a.relu = 1;
        tc_launch(a);
        // layer 2: i1 -> i2
        a.Ahi[0] = i1hi; a.Alo[0] = i1lo;
        a.Bhi[0] = whi + WO_LMSG + 8192; a.Blo[0] = wlo + WO_LMSG + 8192;
        a.bias0 = Lmsg_b + 128; a.Chi = i2hi; a.Clo = i2lo;
        tc_launch(a);
        // layer 3: i2 -> t0 (fp32)
        a.Ahi[0] = i2hi; a.Alo[0] = i2lo;
        a.Bhi[0] = whi + WO_LMSG + 16384; a.Blo[0] = wlo + WO_LMSG + 16384;
        a.bias0 = Lmsg_b + 256; a.Chi = nullptr; a.Clo = nullptr;
        a.C = t0; a.relu = 0;
        tc_launch(a);

        zero_kernel<<<((size_t)NCL * 32 + 255) / 256, 256>>>((float4*)msg, (size_t)NCL * 32);
        scatter_kernel<<<sgrid, sblk>>>(t0, esrc, edst, E, msg);
        cvt_pairs<<<((size_t)NCL * 64 + 255) / 256, 256>>>((const float2*)msg, mhi, mlo, (size_t)NCL * 64);

        // ---- clause gates: msg@CuWih^T + hC@CuWhh^T ----
        a = {};
        a.Ahi[0] = mhi; a.Alo[0] = mlo;
        a.Bhi[0] = whi + WO_CWIH; a.Blo[0] = wlo + WO_CWIH; a.ldb32[0] = 64;
        a.Ahi[1] = hhi + (size_t)V2_ * 64; a.Alo[1] = hlo + (size_t)V2_ * 64;
        a.Bhi[1] = whi + WO_CWHH; a.Blo[1] = wlo + WO_CWHH; a.ldb32[1] = 64;
        a.nTerms = 2; a.bias0 = Cu_bih; a.bias1 = Cu_bhh;
        a.C = gates; a.M = NCL; a.N = 512;
        tc_launch(a);
        lstm_kernel<<<((size_t)NCL * 32 + 255) / 256, 256>>>(
            gates, h + (size_t)V2_ * D_, c + (size_t)V2_ * D_,
            hhi + (size_t)V2_ * 64, hlo + (size_t)V2_ * 64, NCL);

        // ---- C-MLP ----
        a = {};
        a.Ahi[0] = hhi + (size_t)V2_ * 64; a.Alo[0] = hlo + (size_t)V2_ * 64;
        a.Bhi[0] = whi + WO_CMSG; a.Blo[0] = wlo + WO_CMSG; a.ldb32[0] = 64;
        a.nTerms = 1; a.bias0 = Cmsg_b; a.Chi = i1hi; a.Clo = i1lo;
        a.M = NCL; a.N = 128; a.relu = 1;
        tc_launch(a);
        a.Ahi[0] = i1hi; a.Alo[0] = i1lo;
        a.Bhi[0] = whi + WO_CMSG + 8192; a.Blo[0] = wlo + WO_CMSG + 8192;
        a.bias0 = Cmsg_b + 128; a.Chi = i2hi; a.Clo = i2lo;
        tc_launch(a);
        a.Ahi[0] = i2hi; a.Alo[0] = i2lo;
        a.Bhi[0] = whi + WO_CMSG + 16384; a.Blo[0] = wlo + WO_CMSG + 16384;
        a.bias0 = Cmsg_b + 256; a.Chi = nullptr; a.Clo = nullptr;
        a.C = t0; a.relu = 0;
        tc_launch(a);

        zero_kernel<<<((size_t)V2_ * 32 + 255) / 256, 256>>>((float4*)msg, (size_t)V2_ * 32);
        scatter_kernel<<<sgrid, sblk>>>(t0, edst, esrc, E, msg);
        cvt_pairs<<<((size_t)V2_ * 64 + 255) / 256, 256>>>((const float2*)msg, mhi, mlo, (size_t)V2_ * 64);

        // ---- literal gates: msg@LuWih[:, :128]^T + hneg@LuWih[:, 128:]^T + h@LuWhh^T ----
        a = {};
        a.Ahi[0] = mhi; a.Alo[0] = mlo;
        a.Bhi[0] = whi + WO_LWIH; a.Blo[0] = wlo + WO_LWIH; a.ldb32[0] = 128; a.bko32[0] = 0;
        a.Ahi[1] = hhi; a.Alo[1] = hlo; a.negflip[1] = 1;
        a.Bhi[1] = whi + WO_LWIH; a.Blo[1] = wlo + WO_LWIH; a.ldb32[1] = 128; a.bko32[1] = 64;
        a.Ahi[2] = hhi; a.Alo[2] = hlo;
        a.Bhi[2] = whi + WO_LWHH; a.Blo[2] = wlo + WO_LWHH; a.ldb32[2] = 64;
        a.nTerms = 3; a.bias0 = Lu_bih; a.bias1 = Lu_bhh;
        a.C = gates; a.M = V2_; a.N = 512;
        tc_launch(a);
        lstm_kernel<<<((size_t)V2_ * 32 + 255) / 256, 256>>>(gates, h, c, hhi, hlo, V2_);
    }

    copy_kernel<<<((size_t)NTOTAL * 32 + 255) / 256, 256>>>(
        (const float4*)h, (float4*)d_out, (size_t)NTOTAL * 32);
}

// round 12
// speedup vs baseline: 1.1916x; 1.1016x over previous
#include <cuda_runtime.h>
#include <cuda_bf16.h>
#include <cstdint>

#define D_      128
#define NVARS   50000
#define V2_     100000
#define NCL     200000
#define NTOTAL  300000
#define NROUNDS 16

// ---------------- persistent scratch ---------------------------------------
__device__ float g_h[(size_t)NTOTAL * D_];
__device__ float g_c[(size_t)NTOTAL * D_];
__device__ float g_msg[(size_t)NCL * D_];
__device__ float g_t0[(size_t)NCL * D_];
__device__ float g_gates[(size_t)NCL * 4 * D_];

// bf16 hi/lo mirrors (u32 = packed bf16x2, 64 u32 per 128-float row)
__device__ uint32_t g_hhi[(size_t)NTOTAL * 64];
__device__ uint32_t g_hlo[(size_t)NTOTAL * 64];
__device__ uint32_t g_mhi[(size_t)NCL * 64];
__device__ uint32_t g_mlo[(size_t)NCL * 64];
// weights: Lmsg(24576) Cmsg(24576) CuWih(32768) CuWhh(32768) LuWih(65536) LuWhh(32768)
#define WO_LMSG  0
#define WO_CMSG  24576
#define WO_CWIH  49152
#define WO_CWHH  81920
#define WO_LWIH  114688
#define WO_LWHH  180224
#define W_TOTAL  212992
__device__ uint32_t g_whi[W_TOTAL];
__device__ uint32_t g_wlo[W_TOTAL];

// ---------------- helpers ---------------------------------------------------
__device__ __forceinline__ void cvt2(float x, float y, uint32_t& hi, uint32_t& lo) {
    __nv_bfloat16 hx = __float2bfloat16_rn(x);
    __nv_bfloat16 hy = __float2bfloat16_rn(y);
    __nv_bfloat162 hp = __halves2bfloat162(hx, hy);
    hi = *(uint32_t*)&hp;
    __nv_bfloat16 lx = __float2bfloat16_rn(x - __bfloat162float(hx));
    __nv_bfloat16 ly = __float2bfloat16_rn(y - __bfloat162float(hy));
    __nv_bfloat162 lp = __halves2bfloat162(lx, ly);
    lo = *(uint32_t*)&lp;
}

__device__ __forceinline__ void mma_bf16(float* d, const uint32_t* a, uint32_t b0, uint32_t b1) {
    asm volatile(
        "mma.sync.aligned.m16n8k16.row.col.f32.bf16.bf16.f32 "
        "{%0,%1,%2,%3}, {%4,%5,%6,%7}, {%8,%9}, {%0,%1,%2,%3};\n"
        : "+f"(d[0]), "+f"(d[1]), "+f"(d[2]), "+f"(d[3])
        : "r"(a[0]), "r"(a[1]), "r"(a[2]), "r"(a[3]), "r"(b0), "r"(b1));
}

__device__ __forceinline__ uint32_t smem_u32(const void* p) {
    uint32_t a;
    asm("{ .reg .u64 t; cvta.to.shared.u64 t, %1; cvt.u32.u64 %0, t; }" : "=r"(a) : "l"(p));
    return a;
}

__device__ __forceinline__ void cp16(uint32_t saddr, const void* g, bool pred) {
    int sz = pred ? 16 : 0;
    asm volatile("cp.async.cg.shared.global [%0], [%1], 16, %2;"
                 :: "r"(saddr), "l"(g), "r"(sz));
}
#define CP_COMMIT() asm volatile("cp.async.commit_group;" ::: "memory")

#define ASTR 36
#define SUB  4608                       // u32 per subtile (128*ASTR)
#define TILE_U32 (4 * SUB)              // one K=128 hi/lo tile pair group (2 halves x hi/lo)
#define SMEM_FUSED ((size_t)(TILE_U32 * 3) * 4)   // 221184 B (A + 2 W bufs | 2A + 1 W buf)

// fill one (half, hi+lo) pair: 128 rows x 32 u32, 512 threads, ld = 64 u32/row
__device__ __forceinline__ void fill_pair(uint32_t sb, uint32_t dst_u32,
                                          const uint32_t* __restrict__ ghi,
                                          const uint32_t* __restrict__ glo,
                                          int rowbase, int kh, int M, int tid,
                                          int nflip) {
#pragma unroll
    for (int i = 0; i < 2; ++i) {
        int f = i * 512 + tid;
        int r = f >> 3, cch = f & 7;
        int gr = rowbase + r;
        bool p = gr < M;
        int src = p ? gr : 0;
        if (nflip) src = (src < NVARS) ? src + NVARS : src - NVARS;
        size_t go = (size_t)src * 64 + kh * 32 + cch * 4;
        uint32_t so = sb + (dst_u32 + (uint32_t)(r * ASTR + cch * 4)) * 4;
        cp16(so, ghi + go, p);
        cp16(so + SUB * 4, glo + go, p);
    }
}

// compute one K=64 half: acc += A(half)@W(half)^T, 16 warps, 32x32 warp tiles
__device__ __forceinline__ void compute_half(const uint32_t* __restrict__ SA,
                                             const uint32_t* __restrict__ SW,
                                             float acc[2][4][4],
                                             int wm, int wn, int g, int t) {
    const uint32_t* SAh = SA;
    const uint32_t* SAl = SA + SUB;
    const uint32_t* SBh = SW;
    const uint32_t* SBl = SW + SUB;
#pragma unroll
    for (int ks = 0; ks < 4; ++ks) {
        const int c0 = ks * 8 + t;
        uint32_t ah[2][4], al[2][4];
#pragma unroll
        for (int mf = 0; mf < 2; ++mf) {
            const int r = wm + mf * 16 + g;
            const uint32_t* p = SAh + r * ASTR + c0;
            ah[mf][0] = p[0]; ah[mf][1] = p[8 * ASTR];
            ah[mf][2] = p[4]; ah[mf][3] = p[8 * ASTR + 4];
            const uint32_t* q = SAl + r * ASTR + c0;
            al[mf][0] = q[0]; al[mf][1] = q[8 * ASTR];
            al[mf][2] = q[4]; al[mf][3] = q[8 * ASTR + 4];
        }
#pragma unroll
        for (int nf = 0; nf < 4; ++nf) {
            const int nr = wn + nf * 8 + g;
            const uint32_t* pb = SBh + nr * ASTR + c0;
            uint32_t bh0 = pb[0], bh1 = pb[4];
            const uint32_t* qb = SBl + nr * ASTR + c0;
            uint32_t bl0 = qb[0], bl1 = qb[4];
#pragma unroll
            for (int mf = 0; mf < 2; ++mf) {
                mma_bf16(acc[mf][nf], ah[mf], bh0, bh1);
                mma_bf16(acc[mf][nf], ah[mf], bl0, bl1);
                mma_bf16(acc[mf][nf], al[mf], bh0, bh1);
            }
        }
    }
}

// ---------------- fused 3-layer MLP -----------------------------------------
// out[M,128] = L3(relu(L2(relu(L1(A)))));  W = 3 x [128,128], bias = 3 x 128
__global__ __launch_bounds__(512) void mlp3_kernel(
    const uint32_t* __restrict__ Ahi, const uint32_t* __restrict__ Alo,
    const uint32_t* __restrict__ Whi, const uint32_t* __restrict__ Wlo,
    const float* __restrict__ bias, float* __restrict__ Cout, int M) {
    extern __shared__ uint32_t sm[];
    const uint32_t sb = smem_u32(sm);
    const int tid  = threadIdx.x;
    const int wid  = tid >> 5;
    const int lane = tid & 31;
    const int g    = lane >> 2;
    const int t    = lane & 3;
    const int wm   = (wid >> 2) * 32;
    const int wn   = (wid & 3) * 32;
    const int brow = blockIdx.x << 7;

    // A both halves (group 0)
    fill_pair(sb, 0,       Ahi, Alo, brow, 0, M, tid, 0);
    fill_pair(sb, 2 * SUB, Ahi, Alo, brow, 1, M, tid, 0);
    CP_COMMIT();
    // W layer0 (group 1)
    fill_pair(sb, TILE_U32,           Whi, Wlo, 0, 0, 128, tid, 0);
    fill_pair(sb, TILE_U32 + 2 * SUB, Whi, Wlo, 0, 1, 128, tid, 0);
    CP_COMMIT();

#pragma unroll
    for (int layer = 0; layer < 3; ++layer) {
        if (layer < 2) {
            const int nb = (layer + 1) & 1;
            const uint32_t wd = TILE_U32 * (1 + nb);
            fill_pair(sb, wd,           Whi + (layer + 1) * 8192, Wlo + (layer + 1) * 8192, 0, 0, 128, tid, 0);
            fill_pair(sb, wd + 2 * SUB, Whi + (layer + 1) * 8192, Wlo + (layer + 1) * 8192, 0, 1, 128, tid, 0);
            CP_COMMIT();
            asm volatile("cp.async.wait_group 1;" ::: "memory");
        } else {
            asm volatile("cp.async.wait_group 0;" ::: "memory");
        }
        __syncthreads();

        const uint32_t* W = sm + TILE_U32 * (1 + (layer & 1));
        float acc[2][4][4];
#pragma unroll
        for (int mf = 0; mf < 2; ++mf)
#pragma unroll
            for (int nf = 0; nf < 4; ++nf)
#pragma unroll
                for (int k = 0; k < 4; ++k) acc[mf][nf][k] = 0.f;

        compute_half(sm,           W,           acc, wm, wn, g, t);
        compute_half(sm + 2 * SUB, W + 2 * SUB, acc, wm, wn, g, t);
        __syncthreads();

        const float* bl = bias + layer * 128;
        if (layer < 2) {
            // relu + re-split into A smem tile
#pragma unroll
            for (int nf = 0; nf < 4; ++nf) {
                const int col = wn + nf * 8 + 2 * t;
                float b0v = bl[col], b1v = bl[col + 1];
                const int c32 = col >> 1;
                const uint32_t hbase = (c32 >> 5) * (2 * SUB);
                const int off = c32 & 31;
#pragma unroll
                for (int mf = 0; mf < 2; ++mf) {
                    const int r = wm + mf * 16 + g;
                    float x0 = fmaxf(acc[mf][nf][0] + b0v, 0.f);
                    float x1 = fmaxf(acc[mf][nf][1] + b1v, 0.f);
                    float x2 = fmaxf(acc[mf][nf][2] + b0v, 0.f);
                    float x3 = fmaxf(acc[mf][nf][3] + b1v, 0.f);
                    uint32_t hv, lv;
                    cvt2(x0, x1, hv, lv);
                    sm[hbase + r * ASTR + off] = hv;
                    sm[hbase + SUB + r * ASTR + off] = lv;
                    cvt2(x2, x3, hv, lv);
                    sm[hbase + (r + 8) * ASTR + off] = hv;
                    sm[hbase + SUB + (r + 8) * ASTR + off] = lv;
                }
            }
            __syncthreads();
        } else {
            // final: fp32 out
#pragma unroll
            for (int nf = 0; nf < 4; ++nf) {
                const int col = wn + nf * 8 + 2 * t;
                float b0v = bl[col], b1v = bl[col + 1];
#pragma unroll
                for (int mf = 0; mf < 2; ++mf) {
                    const int row = brow + wm + mf * 16 + g;
                    if (row < M)
                        *(float2*)(Cout + (size_t)row * 128 + col) =
                            make_float2(acc[mf][nf][0] + b0v, acc[mf][nf][1] + b1v);
                    if (row + 8 < M)
                        *(float2*)(Cout + (size_t)(row + 8) * 128 + col) =
                            make_float2(acc[mf][nf][2] + b0v, acc[mf][nf][3] + b1v);
                }
            }
        }
    }
}

// ---------------- fused 2-term gates GEMM (N=512, A resident, W streamed) ----
__global__ __launch_bounds__(512) void gates2_kernel(
    const uint32_t* __restrict__ A0hi, const uint32_t* __restrict__ A0lo,
    const uint32_t* __restrict__ A1hi, const uint32_t* __restrict__ A1lo,
    const uint32_t* __restrict__ Wihhi, const uint32_t* __restrict__ Wihlo,
    const uint32_t* __restrict__ Whhhi, const uint32_t* __restrict__ Whhlo,
    const float* __restrict__ bih, const float* __restrict__ bhh,
    float* __restrict__ gates, int M) {
    extern __shared__ uint32_t sm[];
    const uint32_t sb = smem_u32(sm);
    const int tid  = threadIdx.x;
    const int wid  = tid >> 5;
    const int lane = tid & 31;
    const int g    = lane >> 2;
    const int t    = lane & 3;
    const int wm   = (wid >> 2) * 32;
    const int wn   = (wid & 3) * 32;
    const int brow = blockIdx.x << 7;

    // A: term0 @0, term1 @TILE_U32 (group 0)
    fill_pair(sb, 0,                  A0hi, A0lo, brow, 0, M, tid, 0);
    fill_pair(sb, 2 * SUB,            A0hi, A0lo, brow, 1, M, tid, 0);
    fill_pair(sb, TILE_U32,           A1hi, A1lo, brow, 0, M, tid, 0);
    fill_pair(sb, TILE_U32 + 2 * SUB, A1hi, A1lo, brow, 1, M, tid, 0);
    CP_COMMIT();

    const uint32_t WB = 2 * TILE_U32;
    for (int nt = 0; nt < 4; ++nt) {
        float acc[2][4][4];
#pragma unroll
        for (int mf = 0; mf < 2; ++mf)
#pragma unroll
            for (int nf = 0; nf < 4; ++nf)
#pragma unroll
                for (int k = 0; k < 4; ++k) acc[mf][nf][k] = 0.f;

#pragma unroll
        for (int term = 0; term < 2; ++term) {
            const uint32_t* wh = term ? Whhhi : Wihhi;
            const uint32_t* wl = term ? Whhlo : Wihlo;
            fill_pair(sb, WB * 4 / 4, wh, wl, nt * 128, 0, 512, tid, 0);
            CP_COMMIT();
            fill_pair(sb, WB + 2 * SUB, wh, wl, nt * 128, 1, 512, tid, 0);
            CP_COMMIT();
            asm volatile("cp.async.wait_group 1;" ::: "memory");
            __syncthreads();
            compute_half(sm + term * TILE_U32, sm + WB, acc, wm, wn, g, t);
            asm volatile("cp.async.wait_group 0;" ::: "memory");
            __syncthreads();
            compute_half(sm + term * TILE_U32 + 2 * SUB, sm + WB + 2 * SUB, acc, wm, wn, g, t);
            __syncthreads();
        }

        // epilogue: fp32 gates, cols nt*128 + ...
#pragma unroll
        for (int nf = 0; nf < 4; ++nf) {
            const int col = nt * 128 + wn + nf * 8 + 2 * t;
            float b0v = bih[col] + bhh[col];
            float b1v = bih[col + 1] + bhh[col + 1];
#pragma unroll
            for (int mf = 0; mf < 2; ++mf) {
                const int row = brow + wm + mf * 16 + g;
                if (row < M)
                    *(float2*)(gates + (size_t)row * 512 + col) =
                        make_float2(acc[mf][nf][0] + b0v, acc[mf][nf][1] + b1v);
                if (row + 8 < M)
                    *(float2*)(gates + (size_t)(row + 8) * 512 + col) =
                        make_float2(acc[mf][nf][2] + b0v, acc[mf][nf][3] + b1v);
            }
        }
    }
}

// ---------------- generic GEMM (literal 3-term gates only) ------------------
#define STAGE_U32 (4 * 128 * ASTR)
#define SMEM_TC_BYTES (2 * STAGE_U32 * 4)

struct TcArgs {
    const uint32_t *Ahi[3], *Alo[3];
    int negflip[3];
    const uint32_t *Bhi[3], *Blo[3];
    int ldb32[3], bko32[3];
    int nTerms;
    const float *bias0, *bias1;
    float* C;
    int M, N;
};

__device__ __forceinline__ void fill_stage(const TcArgs& a, int s, uint32_t sbase,
                                           int brow, int bcol, int tid) {
    const int term = s >> 1, kh = s & 1, b = s & 1;
    const uint32_t st = sbase + (uint32_t)b * (STAGE_U32 * 4);
    const uint32_t* gah = a.Ahi[term];
    const uint32_t* gal = a.Alo[term];
    const int nflip = a.negflip[term];
#pragma unroll
    for (int i = 0; i < 2; ++i) {
        int f = i * 512 + tid;
        int r = f >> 3, cch = f & 7;
        int gr = brow + r;
        bool p = gr < a.M;
        int src = p ? gr : 0;
        if (nflip) src = (src < NVARS) ? src + NVARS : src - NVARS;
        size_t go = (size_t)src * 64 + kh * 32 + cch * 4;
        uint32_t so = st + (uint32_t)(r * ASTR + cch * 4) * 4;
        cp16(so, gah + go, p);
        cp16(so + SUB * 4, gal + go, p);
    }
    const uint32_t* gbh = a.Bhi[term];
    const uint32_t* gbl = a.Blo[term];
    const int ldb = a.ldb32[term], bko = a.bko32[term];
#pragma unroll
    for (int i = 0; i < 2; ++i) {
        int f = i * 512 + tid;
        int r = f >> 3, cch = f & 7;
        size_t go = (size_t)(bcol + r) * ldb + bko + kh * 32 + cch * 4;
        uint32_t so = st + (uint32_t)(2 * SUB + r * ASTR + cch * 4) * 4;
        cp16(so, gbh + go, true);
        cp16(so + SUB * 4, gbl + go, true);
    }
    CP_COMMIT();
}

__global__ __launch_bounds__(512) void tc_gemm(TcArgs a) {
    extern __shared__ uint32_t sm[];
    const uint32_t sbase = smem_u32(sm);
    const int tid  = threadIdx.x;
    const int wid  = tid >> 5;
    const int lane = tid & 31;
    const int g    = lane >> 2;
    const int t    = lane & 3;
    const int wm   = (wid >> 2) * 32;
    const int wn   = (wid & 3) * 32;
    const int brow = blockIdx.x << 7;
    const int bcol = blockIdx.y << 7;

    float acc[2][4][4];
#pragma unroll
    for (int mf = 0; mf < 2; ++mf)
#pragma unroll
        for (int nf = 0; nf < 4; ++nf)
#pragma unroll
            for (int k = 0; k < 4; ++k) acc[mf][nf][k] = 0.f;

    const int nst = a.nTerms * 2;
    fill_stage(a, 0, sbase, brow, bcol, tid);
    fill_stage(a, 1, sbase, brow, bcol, tid);

    for (int s = 0; s < nst; ++s) {
        const int b = s & 1;
        if (s + 1 < nst) asm volatile("cp.async.wait_group 1;" ::: "memory");
        else             asm volatile("cp.async.wait_group 0;" ::: "memory");
        __syncthreads();
        uint32_t* st = sm + b * STAGE_U32;
        compute_half(st, st + 2 * SUB, acc, wm, wn, g, t);
        __syncthreads();
        if (s + 2 < nst) fill_stage(a, s + 2, sbase, brow, bcol, tid);
    }

#pragma unroll
    for (int nf = 0; nf < 4; ++nf) {
        const int col = bcol + wn + nf * 8 + 2 * t;
        float b0v = a.bias0[col], b1v = a.bias0[col + 1];
        if (a.bias1) { b0v += a.bias1[col]; b1v += a.bias1[col + 1]; }
#pragma unroll
        for (int mf = 0; mf < 2; ++mf) {
            const int row = brow + wm + mf * 16 + g;
            if (row < a.M)
                *(float2*)(a.C + (size_t)row * a.N + col) =
                    make_float2(acc[mf][nf][0] + b0v, acc[mf][nf][1] + b1v);
            if (row + 8 < a.M)
                *(float2*)(a.C + (size_t)(row + 8) * a.N + col) =
                    make_float2(acc[mf][nf][2] + b0v, acc[mf][nf][3] + b1v);
        }
    }
}

// ---------------- edge scatter-add -----------------------------------------
__global__ void scatter_kernel(const float* __restrict__ rows,
                               const int* __restrict__ gidx,
                               const int* __restrict__ sidx,
                               int E, float* __restrict__ out) {
    int e = blockIdx.x * 8 + threadIdx.y;
    if (e >= E) return;
    int s = gidx[e];
    int d = sidx[e];
    float4 v = *(const float4*)(rows + (size_t)s * D_ + threadIdx.x * 4);
    float* p = out + (size_t)d * D_ + threadIdx.x * 4;
    asm volatile("red.global.add.v4.f32 [%0], {%1, %2, %3, %4};"
                 :: "l"(p), "f"(v.x), "f"(v.y), "f"(v.z), "f"(v.w)
                 : "memory");
}

// ---------------- elementwise ----------------------------------------------
__device__ __forceinline__ float sigf(float x) {
    return __fdividef(1.f, 1.f + __expf(-x));
}
__device__ __forceinline__ float tanhfast(float x) {
    return __fdividef(2.f, 1.f + __expf(-2.f * x)) - 1.f;
}

__global__ void lstm_kernel(const float* __restrict__ gates,
                            float* __restrict__ h, float* __restrict__ c,
                            uint32_t* __restrict__ hhi, uint32_t* __restrict__ hlo,
                            int M) {
    size_t idx = (size_t)blockIdx.x * blockDim.x + threadIdx.x;
    if (idx >= (size_t)M * 32) return;
    size_t r = idx >> 5;
    int q = (int)(idx & 31) * 4;
    const float* gb = gates + r * 512;
    float4 gi = *(const float4*)(gb + q);
    float4 gf = *(const float4*)(gb + 128 + q);
    float4 gg = *(const float4*)(gb + 256 + q);
    float4 go = *(const float4*)(gb + 384 + q);
    float4 cc = *(const float4*)(c + r * D_ + q);
    float4 c2, hh;
    c2.x = sigf(gf.x) * cc.x + sigf(gi.x) * tanhfast(gg.x); hh.x = sigf(go.x) * tanhfast(c2.x);
    c2.y = sigf(gf.y) * cc.y + sigf(gi.y) * tanhfast(gg.y); hh.y = sigf(go.y) * tanhfast(c2.y);
    c2.z = sigf(gf.z) * cc.z + sigf(gi.z) * tanhfast(gg.z); hh.z = sigf(go.z) * tanhfast(c2.z);
    c2.w = sigf(gf.w) * cc.w + sigf(gi.w) * tanhfast(gg.w); hh.w = sigf(go.w) * tanhfast(c2.w);
    *(float4*)(c + r * D_ + q) = c2;
    *(float4*)(h + r * D_ + q) = hh;
    uint32_t h0, l0, h1, l1;
    cvt2(hh.x, hh.y, h0, l0);
    cvt2(hh.z, hh.w, h1, l1);
    *(uint2*)(hhi + r * 64 + (q >> 1)) = make_uint2(h0, h1);
    *(uint2*)(hlo + r * 64 + (q >> 1)) = make_uint2(l0, l1);
}

__global__ void init_kernel(const float* __restrict__ lw, const float* __restrict__ lb,
                            const float* __restrict__ cw, const float* __restrict__ cb,
                            float* __restrict__ h,
                            uint32_t* __restrict__ hhi, uint32_t* __restrict__ hlo) {
    int tid = threadIdx.x;           // 0..63
    size_t row = blockIdx.x;
    int d0 = tid * 2;
    float v0, v1;
    if (row < V2_) { v0 = lw[d0] + lb[d0]; v1 = lw[d0 + 1] + lb[d0 + 1]; }
    else           { v0 = cw[d0] + cb[d0]; v1 = cw[d0 + 1] + cb[d0 + 1]; }
    h[row * D_ + d0] = v0;
    h[row * D_ + d0 + 1] = v1;
    uint32_t hv, lv;
    cvt2(v0, v1, hv, lv);
    hhi[row * 64 + tid] = hv;
    hlo[row * 64 + tid] = lv;
}

__global__ void cvt_pairs(const float2* __restrict__ src,
                          uint32_t* __restrict__ hi, uint32_t* __restrict__ lo, size_t n) {
    size_t i = (size_t)blockIdx.x * blockDim.x + threadIdx.x;
    if (i >= n) return;
    float2 v = src[i];
    uint32_t hv, lv;
    cvt2(v.x, v.y, hv, lv);
    hi[i] = hv; lo[i] = lv;
}

__global__ void zero_kernel(float4* __restrict__ p, size_t n4) {
    size_t i = (size_t)blockIdx.x * blockDim.x + threadIdx.x;
    if (i < n4) p[i] = make_float4(0.f, 0.f, 0.f, 0.f);
}

__global__ void copy_kernel(const float4* __restrict__ src, float4* __restrict__ dst, size_t n4) {
    size_t i = (size_t)blockIdx.x * blockDim.x + threadIdx.x;
    if (i < n4) dst[i] = src[i];
}

// ---------------- host -------------------------------------------------------
extern "C" void kernel_launch(void* const* d_in, const int* in_sizes, int n_in,
                              void* d_out, int out_size) {
    const float* L_init_w = (const float*)d_in[0];
    const float* L_init_b = (const float*)d_in[1];
    const float* C_init_w = (const float*)d_in[2];
    const float* C_init_b = (const float*)d_in[3];
    const float* Lmsg_w   = (const float*)d_in[4];
    const float* Lmsg_b   = (const float*)d_in[5];
    const float* Cmsg_w   = (const float*)d_in[6];
    const float* Cmsg_b   = (const float*)d_in[7];
    const float* Cu_wih   = (const float*)d_in[8];
    const float* Cu_whh   = (const float*)d_in[9];
    const float* Cu_bih   = (const float*)d_in[10];
    const float* Cu_bhh   = (const float*)d_in[11];
    const float* Lu_wih   = (const float*)d_in[12];
    const float* Lu_whh   = (const float*)d_in[13];
    const float* Lu_bih   = (const float*)d_in[14];
    const float* Lu_bhh   = (const float*)d_in[15];
    const int*   esrc     = (const int*)d_in[16];
    const int*   edst     = (const int*)d_in[17];
    const int E = in_sizes[16];

    static int smem_set = 0;
    if (!smem_set) {
        cudaFuncSetAttribute(tc_gemm, cudaFuncAttributeMaxDynamicSharedMemorySize, SMEM_TC_BYTES);
        cudaFuncSetAttribute(mlp3_kernel, cudaFuncAttributeMaxDynamicSharedMemorySize, SMEM_FUSED);
        cudaFuncSetAttribute(gates2_kernel, cudaFuncAttributeMaxDynamicSharedMemorySize, SMEM_FUSED);
        smem_set = 1;
    }

    float *h, *c, *msg, *t0, *gates;
    uint32_t *hhi, *hlo, *mhi, *mlo, *whi, *wlo;
    cudaGetSymbolAddress((void**)&h,     g_h);
    cudaGetSymbolAddress((void**)&c,     g_c);
    cudaGetSymbolAddress((void**)&msg,   g_msg);
    cudaGetSymbolAddress((void**)&t0,    g_t0);
    cudaGetSymbolAddress((void**)&gates, g_gates);
    cudaGetSymbolAddress((void**)&hhi,   g_hhi);
    cudaGetSymbolAddress((void**)&hlo,   g_hlo);
    cudaGetSymbolAddress((void**)&mhi,   g_mhi);
    cudaGetSymbolAddress((void**)&mlo,   g_mlo);
    cudaGetSymbolAddress((void**)&whi,   g_whi);
    cudaGetSymbolAddress((void**)&wlo,   g_wlo);

    // ---- pre-convert weights ----
    cvt_pairs<<<(24576 + 255) / 256, 256>>>((const float2*)Lmsg_w, whi + WO_LMSG, wlo + WO_LMSG, 24576);
    cvt_pairs<<<(24576 + 255) / 256, 256>>>((const float2*)Cmsg_w, whi + WO_CMSG, wlo + WO_CMSG, 24576);
    cvt_pairs<<<(32768 + 255) / 256, 256>>>((const float2*)Cu_wih, whi + WO_CWIH, wlo + WO_CWIH, 32768);
    cvt_pairs<<<(32768 + 255) / 256, 256>>>((const float2*)Cu_whh, whi + WO_CWHH, wlo + WO_CWHH, 32768);
    cvt_pairs<<<(65536 + 255) / 256, 256>>>((const float2*)Lu_wih, whi + WO_LWIH, wlo + WO_LWIH, 65536);
    cvt_pairs<<<(32768 + 255) / 256, 256>>>((const float2*)Lu_whh, whi + WO_LWHH, wlo + WO_LWHH, 32768);

    init_kernel<<<NTOTAL, 64>>>(L_init_w, L_init_b, C_init_w, C_init_b, h, hhi, hlo);
    zero_kernel<<<((size_t)NTOTAL * 32 + 255) / 256, 256>>>((float4*)c, (size_t)NTOTAL * 32);

    dim3 sblk(32, 8);
    int sgrid = (E + 7) / 8;
    const int gv = (V2_ + 127) >> 7;    // 782
    const int gc = (NCL + 127) >> 7;    // 1563

    for (int r = 0; r < NROUNDS; ++r) {
        // ---- L-MLP fused (3 layers) -> t0 ----
        mlp3_kernel<<<gv, 512, SMEM_FUSED>>>(hhi, hlo, whi + WO_LMSG, wlo + WO_LMSG,
                                             Lmsg_b, t0, V2_);
        zero_kernel<<<((size_t)NCL * 32 + 255) / 256, 256>>>((float4*)msg, (size_t)NCL * 32);
        scatter_kernel<<<sgrid, sblk>>>(t0, esrc, edst, E, msg);
        cvt_pairs<<<((size_t)NCL * 64 + 255) / 256, 256>>>((const float2*)msg, mhi, mlo, (size_t)NCL * 64);

        // ---- clause gates fused (2 terms, 4 N-tiles in-CTA) ----
        gates2_kernel<<<gc, 512, SMEM_FUSED>>>(
            mhi, mlo, hhi + (size_t)V2_ * 64, hlo + (size_t)V2_ * 64,
            whi + WO_CWIH, wlo + WO_CWIH, whi + WO_CWHH, wlo + WO_CWHH,
            Cu_bih, Cu_bhh, gates, NCL);
        lstm_kernel<<<((size_t)NCL * 32 + 255) / 256, 256>>>(
            gates, h + (size_t)V2_ * D_, c + (size_t)V2_ * D_,
            hhi + (size_t)V2_ * 64, hlo + (size_t)V2_ * 64, NCL);

        // ---- C-MLP fused -> t0 ----
        mlp3_kernel<<<gc, 512, SMEM_FUSED>>>(hhi + (size_t)V2_ * 64, hlo + (size_t)V2_ * 64,
                                             whi + WO_CMSG, wlo + WO_CMSG,
                                             Cmsg_b, t0, NCL);
        zero_kernel<<<((size_t)V2_ * 32 + 255) / 256, 256>>>((float4*)msg, (size_t)V2_ * 32);
        scatter_kernel<<<sgrid, sblk>>>(t0, edst, esrc, E, msg);
        cvt_pairs<<<((size_t)V2_ * 64 + 255) / 256, 256>>>((const float2*)msg, mhi, mlo, (size_t)V2_ * 64);

        // ---- literal gates (3-term, generic path) ----
        TcArgs a = {};
        a.Ahi[0] = mhi; a.Alo[0] = mlo;
        a.Bhi[0] = whi + WO_LWIH; a.Blo[0] = wlo + WO_LWIH; a.ldb32[0] = 128; a.bko32[0] = 0;
        a.Ahi[1] = hhi; a.Alo[1] = hlo; a.negflip[1] = 1;
        a.Bhi[1] = whi + WO_LWIH; a.Blo[1] = wlo + WO_LWIH; a.ldb32[1] = 128; a.bko32[1] = 64;
        a.Ahi[2] = hhi; a.Alo[2] = hlo;
        a.Bhi[2] = whi + WO_LWHH; a.Blo[2] = wlo + WO_LWHH; a.ldb32[2] = 64;
        a.nTerms = 3; a.bias0 = Lu_bih; a.bias1 = Lu_bhh;
        a.C = gates; a.M = V2_; a.N = 512;
        dim3 grid(gv, 4);
        tc_gemm<<<grid, 512, SMEM_TC_BYTES>>>(a);
        lstm_kernel<<<((size_t)V2_ * 32 + 255) / 256, 256>>>(gates, h, c, hhi, hlo, V2_);
    }

    copy_kernel<<<((size_t)NTOTAL * 32 + 255) / 256, 256>>>(
        (const float4*)h, (float4*)d_out, (size_t)NTOTAL * 32);
}

// round 14
// speedup vs baseline: 1.3265x; 1.1132x over previous
#include <cuda_runtime.h>
#include <cuda_bf16.h>
#include <cstdint>

#define D_      128
#define NVARS   50000
#define V2_     100000
#define NCL     200000
#define NTOTAL  300000
#define NROUNDS 16
#define EDG     800000

// ---------------- persistent scratch ---------------------------------------
__device__ float g_h[(size_t)NTOTAL * D_];
__device__ float g_c[(size_t)NTOTAL * D_];
__device__ float g_t0[(size_t)NCL * D_];
__device__ float g_gates[(size_t)NCL * 4 * D_];

// bf16 hi/lo mirrors (u32 = packed bf16x2, 64 u32 per 128-float row)
__device__ uint32_t g_hhi[(size_t)NTOTAL * 64];
__device__ uint32_t g_hlo[(size_t)NTOTAL * 64];
__device__ uint32_t g_mhi[(size_t)NCL * 64];
__device__ uint32_t g_mlo[(size_t)NCL * 64];
// weights
#define WO_LMSG  0
#define WO_CMSG  24576
#define WO_CWIH  49152
#define WO_CWHH  81920
#define WO_LWIH  114688
#define WO_LWHH  180224
#define W_TOTAL  212992
__device__ uint32_t g_whi[W_TOTAL];
__device__ uint32_t g_wlo[W_TOTAL];

// CSR edge structures (built once per launch)
__device__ int g_cntC[NCL + 1];
__device__ int g_cntL[V2_ + 1];
__device__ int g_curC[NCL];
__device__ int g_curL[V2_];
__device__ int g_srcC[EDG];
__device__ int g_srcL[EDG];

// ---------------- helpers ---------------------------------------------------
__device__ __forceinline__ void cvt2(float x, float y, uint32_t& hi, uint32_t& lo) {
    __nv_bfloat16 hx = __float2bfloat16_rn(x);
    __nv_bfloat16 hy = __float2bfloat16_rn(y);
    __nv_bfloat162 hp = __halves2bfloat162(hx, hy);
    hi = *(uint32_t*)&hp;
    __nv_bfloat16 lx = __float2bfloat16_rn(x - __bfloat162float(hx));
    __nv_bfloat16 ly = __float2bfloat16_rn(y - __bfloat162float(hy));
    __nv_bfloat162 lp = __halves2bfloat162(lx, ly);
    lo = *(uint32_t*)&lp;
}

__device__ __forceinline__ void mma_bf16(float* d, const uint32_t* a, uint32_t b0, uint32_t b1) {
    asm volatile(
        "mma.sync.aligned.m16n8k16.row.col.f32.bf16.bf16.f32 "
        "{%0,%1,%2,%3}, {%4,%5,%6,%7}, {%8,%9}, {%0,%1,%2,%3};\n"
        : "+f"(d[0]), "+f"(d[1]), "+f"(d[2]), "+f"(d[3])
        : "r"(a[0]), "r"(a[1]), "r"(a[2]), "r"(a[3]), "r"(b0), "r"(b1));
}

__device__ __forceinline__ uint32_t smem_u32(const void* p) {
    uint32_t a;
    asm("{ .reg .u64 t; cvta.to.shared.u64 t, %1; cvt.u32.u64 %0, t; }" : "=r"(a) : "l"(p));
    return a;
}

__device__ __forceinline__ void cp16(uint32_t saddr, const void* g, bool pred) {
    int sz = pred ? 16 : 0;
    asm volatile("cp.async.cg.shared.global [%0], [%1], 16, %2;"
                 :: "r"(saddr), "l"(g), "r"(sz));
}
#define CP_COMMIT() asm volatile("cp.async.commit_group;" ::: "memory")

#define ASTR 36
#define SUB  4608
#define TILE_U32 (4 * SUB)
#define SMEM_FUSED ((size_t)(TILE_U32 * 3) * 4)   // 221184 B

__device__ __forceinline__ void fill_pair(uint32_t sb, uint32_t dst_u32,
                                          const uint32_t* __restrict__ ghi,
                                          const uint32_t* __restrict__ glo,
                                          int rowbase, int kh, int M, int tid,
                                          int nflip) {
#pragma unroll
    for (int i = 0; i < 2; ++i) {
        int f = i * 512 + tid;
        int r = f >> 3, cch = f & 7;
        int gr = rowbase + r;
        bool p = gr < M;
        int src = p ? gr : 0;
        if (nflip) src = (src < NVARS) ? src + NVARS : src - NVARS;
        size_t go = (size_t)src * 64 + kh * 32 + cch * 4;
        uint32_t so = sb + (dst_u32 + (uint32_t)(r * ASTR + cch * 4)) * 4;
        cp16(so, ghi + go, p);
        cp16(so + SUB * 4, glo + go, p);
    }
}

__device__ __forceinline__ void compute_half(const uint32_t* __restrict__ SA,
                                             const uint32_t* __restrict__ SW,
                                             float acc[2][4][4],
                                             int wm, int wn, int g, int t) {
    const uint32_t* SAh = SA;
    const uint32_t* SAl = SA + SUB;
    const uint32_t* SBh = SW;
    const uint32_t* SBl = SW + SUB;
#pragma unroll
    for (int ks = 0; ks < 4; ++ks) {
        const int c0 = ks * 8 + t;
        uint32_t ah[2][4], al[2][4];
#pragma unroll
        for (int mf = 0; mf < 2; ++mf) {
            const int r = wm + mf * 16 + g;
            const uint32_t* p = SAh + r * ASTR + c0;
            ah[mf][0] = p[0]; ah[mf][1] = p[8 * ASTR];
            ah[mf][2] = p[4]; ah[mf][3] = p[8 * ASTR + 4];
            const uint32_t* q = SAl + r * ASTR + c0;
            al[mf][0] = q[0]; al[mf][1] = q[8 * ASTR];
            al[mf][2] = q[4]; al[mf][3] = q[8 * ASTR + 4];
        }
#pragma unroll
        for (int nf = 0; nf < 4; ++nf) {
            const int nr = wn + nf * 8 + g;
            const uint32_t* pb = SBh + nr * ASTR + c0;
            uint32_t bh0 = pb[0], bh1 = pb[4];
            const uint32_t* qb = SBl + nr * ASTR + c0;
            uint32_t bl0 = qb[0], bl1 = qb[4];
#pragma unroll
            for (int mf = 0; mf < 2; ++mf) {
                mma_bf16(acc[mf][nf], ah[mf], bh0, bh1);
                mma_bf16(acc[mf][nf], ah[mf], bl0, bl1);
                mma_bf16(acc[mf][nf], al[mf], bh0, bh1);
            }
        }
    }
}

// ---------------- fused 3-layer MLP -----------------------------------------
__global__ __launch_bounds__(512) void mlp3_kernel(
    const uint32_t* __restrict__ Ahi, const uint32_t* __restrict__ Alo,
    const uint32_t* __restrict__ Whi, const uint32_t* __restrict__ Wlo,
    const float* __restrict__ bias, float* __restrict__ Cout, int M) {
    extern __shared__ uint32_t sm[];
    const uint32_t sb = smem_u32(sm);
    const int tid  = threadIdx.x;
    const int wid  = tid >> 5;
    const int lane = tid & 31;
    const int g    = lane >> 2;
    const int t    = lane & 3;
    const int wm   = (wid >> 2) * 32;
    const int wn   = (wid & 3) * 32;
    const int brow = blockIdx.x << 7;

    fill_pair(sb, 0,       Ahi, Alo, brow, 0, M, tid, 0);
    fill_pair(sb, 2 * SUB, Ahi, Alo, brow, 1, M, tid, 0);
    CP_COMMIT();
    fill_pair(sb, TILE_U32,           Whi, Wlo, 0, 0, 128, tid, 0);
    fill_pair(sb, TILE_U32 + 2 * SUB, Whi, Wlo, 0, 1, 128, tid, 0);
    CP_COMMIT();

#pragma unroll
    for (int layer = 0; layer < 3; ++layer) {
        if (layer < 2) {
            const int nb = (layer + 1) & 1;
            const uint32_t wd = TILE_U32 * (1 + nb);
            fill_pair(sb, wd,           Whi + (layer + 1) * 8192, Wlo + (layer + 1) * 8192, 0, 0, 128, tid, 0);
            fill_pair(sb, wd + 2 * SUB, Whi + (layer + 1) * 8192, Wlo + (layer + 1) * 8192, 0, 1, 128, tid, 0);
            CP_COMMIT();
            asm volatile("cp.async.wait_group 1;" ::: "memory");
        } else {
            asm volatile("cp.async.wait_group 0;" ::: "memory");
        }
        __syncthreads();

        const uint32_t* W = sm + TILE_U32 * (1 + (layer & 1));
        float acc[2][4][4];
#pragma unroll
        for (int mf = 0; mf < 2; ++mf)
#pragma unroll
            for (int nf = 0; nf < 4; ++nf)
#pragma unroll
                for (int k = 0; k < 4; ++k) acc[mf][nf][k] = 0.f;

        compute_half(sm,           W,           acc, wm, wn, g, t);
        compute_half(sm + 2 * SUB, W + 2 * SUB, acc, wm, wn, g, t);
        __syncthreads();

        const float* bl = bias + layer * 128;
        if (layer < 2) {
#pragma unroll
            for (int nf = 0; nf < 4; ++nf) {
                const int col = wn + nf * 8 + 2 * t;
                float b0v = bl[col], b1v = bl[col + 1];
                const int c32 = col >> 1;
                const uint32_t hbase = (c32 >> 5) * (2 * SUB);
                const int off = c32 & 31;
#pragma unroll
                for (int mf = 0; mf < 2; ++mf) {
                    const int r = wm + mf * 16 + g;
                    float x0 = fmaxf(acc[mf][nf][0] + b0v, 0.f);
                    float x1 = fmaxf(acc[mf][nf][1] + b1v, 0.f);
                    float x2 = fmaxf(acc[mf][nf][2] + b0v, 0.f);
                    float x3 = fmaxf(acc[mf][nf][3] + b1v, 0.f);
                    uint32_t hv, lv;
                    cvt2(x0, x1, hv, lv);
                    sm[hbase + r * ASTR + off] = hv;
                    sm[hbase + SUB + r * ASTR + off] = lv;
                    cvt2(x2, x3, hv, lv);
                    sm[hbase + (r + 8) * ASTR + off] = hv;
                    sm[hbase + SUB + (r + 8) * ASTR + off] = lv;
                }
            }
            __syncthreads();
        } else {
#pragma unroll
            for (int nf = 0; nf < 4; ++nf) {
                const int col = wn + nf * 8 + 2 * t;
                float b0v = bl[col], b1v = bl[col + 1];
#pragma unroll
                for (int mf = 0; mf < 2; ++mf) {
                    const int row = brow + wm + mf * 16 + g;
                    if (row < M)
                        *(float2*)(Cout + (size_t)row * 128 + col) =
                            make_float2(acc[mf][nf][0] + b0v, acc[mf][nf][1] + b1v);
                    if (row + 8 < M)
                        *(float2*)(Cout + (size_t)(row + 8) * 128 + col) =
                            make_float2(acc[mf][nf][2] + b0v, acc[mf][nf][3] + b1v);
                }
            }
        }
    }
}

// ---------------- fused 2-term gates GEMM ------------------------------------
__global__ __launch_bounds__(512) void gates2_kernel(
    const uint32_t* __restrict__ A0hi, const uint32_t* __restrict__ A0lo,
    const uint32_t* __restrict__ A1hi, const uint32_t* __restrict__ A1lo,
    const uint32_t* __restrict__ Wihhi, const uint32_t* __restrict__ Wihlo,
    const uint32_t* __restrict__ Whhhi, const uint32_t* __restrict__ Whhlo,
    const float* __restrict__ bih, const float* __restrict__ bhh,
    float* __restrict__ gates, int M) {
    extern __shared__ uint32_t sm[];
    const uint32_t sb = smem_u32(sm);
    const int tid  = threadIdx.x;
    const int wid  = tid >> 5;
    const int lane = tid & 31;
    const int g    = lane >> 2;
    const int t    = lane & 3;
    const int wm   = (wid >> 2) * 32;
    const int wn   = (wid & 3) * 32;
    const int brow = blockIdx.x << 7;

    fill_pair(sb, 0,                  A0hi, A0lo, brow, 0, M, tid, 0);
    fill_pair(sb, 2 * SUB,            A0hi, A0lo, brow, 1, M, tid, 0);
    fill_pair(sb, TILE_U32,           A1hi, A1lo, brow, 0, M, tid, 0);
    fill_pair(sb, TILE_U32 + 2 * SUB, A1hi, A1lo, brow, 1, M, tid, 0);
    CP_COMMIT();

    const uint32_t WB = 2 * TILE_U32;
    for (int nt = 0; nt < 4; ++nt) {
        float acc[2][4][4];
#pragma unroll
        for (int mf = 0; mf < 2; ++mf)
#pragma unroll
            for (int nf = 0; nf < 4; ++nf)
#pragma unroll
                for (int k = 0; k < 4; ++k) acc[mf][nf][k] = 0.f;

#pragma unroll
        for (int term = 0; term < 2; ++term) {
            const uint32_t* wh = term ? Whhhi : Wihhi;
            const uint32_t* wl = term ? Whhlo : Wihlo;
            fill_pair(sb, WB, wh, wl, nt * 128, 0, 512, tid, 0);
            CP_COMMIT();
            fill_pair(sb, WB + 2 * SUB, wh, wl, nt * 128, 1, 512, tid, 0);
            CP_COMMIT();
            asm volatile("cp.async.wait_group 1;" ::: "memory");
            __syncthreads();
            compute_half(sm + term * TILE_U32, sm + WB, acc, wm, wn, g, t);
            asm volatile("cp.async.wait_group 0;" ::: "memory");
            __syncthreads();
            compute_half(sm + term * TILE_U32 + 2 * SUB, sm + WB + 2 * SUB, acc, wm, wn, g, t);
            __syncthreads();
        }

#pragma unroll
        for (int nf = 0; nf < 4; ++nf) {
            const int col = nt * 128 + wn + nf * 8 + 2 * t;
            float b0v = bih[col] + bhh[col];
            float b1v = bih[col + 1] + bhh[col + 1];
#pragma unroll
            for (int mf = 0; mf < 2; ++mf) {
                const int row = brow + wm + mf * 16 + g;
                if (row < M)
                    *(float2*)(gates + (size_t)row * 512 + col) =
                        make_float2(acc[mf][nf][0] + b0v, acc[mf][nf][1] + b1v);
                if (row + 8 < M)
                    *(float2*)(gates + (size_t)(row + 8) * 512 + col) =
                        make_float2(acc[mf][nf][2] + b0v, acc[mf][nf][3] + b1v);
            }
        }
    }
}

// ---------------- generic GEMM (literal 3-term gates) ------------------------
#define STAGE_U32 (4 * 128 * ASTR)
#define SMEM_TC_BYTES (2 * STAGE_U32 * 4)

struct TcArgs {
    const uint32_t *Ahi[3], *Alo[3];
    int negflip[3];
    const uint32_t *Bhi[3], *Blo[3];
    int ldb32[3], bko32[3];
    int nTerms;
    const float *bias0, *bias1;
    float* C;
    int M, N;
};

__device__ __forceinline__ void fill_stage(const TcArgs& a, int s, uint32_t sbase,
                                           int brow, int bcol, int tid) {
    const int term = s >> 1, kh = s & 1, b = s & 1;
    const uint32_t st = sbase + (uint32_t)b * (STAGE_U32 * 4);
    const uint32_t* gah = a.Ahi[term];
    const uint32_t* gal = a.Alo[term];
    const int nflip = a.negflip[term];
#pragma unroll
    for (int i = 0; i < 2; ++i) {
        int f = i * 512 + tid;
        int r = f >> 3, cch = f & 7;
        int gr = brow + r;
        bool p = gr < a.M;
        int src = p ? gr : 0;
        if (nflip) src = (src < NVARS) ? src + NVARS : src - NVARS;
        size_t go = (size_t)src * 64 + kh * 32 + cch * 4;
        uint32_t so = st + (uint32_t)(r * ASTR + cch * 4) * 4;
        cp16(so, gah + go, p);
        cp16(so + SUB * 4, gal + go, p);
    }
    const uint32_t* gbh = a.Bhi[term];
    const uint32_t* gbl = a.Blo[term];
    const int ldb = a.ldb32[term], bko = a.bko32[term];
#pragma unroll
    for (int i = 0; i < 2; ++i) {
        int f = i * 512 + tid;
        int r = f >> 3, cch = f & 7;
        size_t go = (size_t)(bcol + r) * ldb + bko + kh * 32 + cch * 4;
        uint32_t so = st + (uint32_t)(2 * SUB + r * ASTR + cch * 4) * 4;
        cp16(so, gbh + go, true);
        cp16(so + SUB * 4, gbl + go, true);
    }
    CP_COMMIT();
}

__global__ __launch_bounds__(512) void tc_gemm(TcArgs a) {
    extern __shared__ uint32_t sm[];
    const uint32_t sbase = smem_u32(sm);
    const int tid  = threadIdx.x;
    const int wid  = tid >> 5;
    const int lane = tid & 31;
    const int g    = lane >> 2;
    const int t    = lane & 3;
    const int wm   = (wid >> 2) * 32;
    const int wn   = (wid & 3) * 32;
    const int brow = blockIdx.x << 7;
    const int bcol = blockIdx.y << 7;

    float acc[2][4][4];
#pragma unroll
    for (int mf = 0; mf < 2; ++mf)
#pragma unroll
        for (int nf = 0; nf < 4; ++nf)
#pragma unroll
            for (int k = 0; k < 4; ++k) acc[mf][nf][k] = 0.f;

    const int nst = a.nTerms * 2;
    fill_stage(a, 0, sbase, brow, bcol, tid);
    fill_stage(a, 1, sbase, brow, bcol, tid);

    for (int s = 0; s < nst; ++s) {
        const int b = s & 1;
        if (s + 1 < nst) asm volatile("cp.async.wait_group 1;" ::: "memory");
        else             asm volatile("cp.async.wait_group 0;" ::: "memory");
        __syncthreads();
        uint32_t* st = sm + b * STAGE_U32;
        compute_half(st, st + 2 * SUB, acc, wm, wn, g, t);
        __syncthreads();
        if (s + 2 < nst) fill_stage(a, s + 2, sbase, brow, bcol, tid);
    }

#pragma unroll
    for (int nf = 0; nf < 4; ++nf) {
        const int col = bcol + wn + nf * 8 + 2 * t;
        float b0v = a.bias0[col], b1v = a.bias0[col + 1];
        if (a.bias1) { b0v += a.bias1[col]; b1v += a.bias1[col + 1]; }
#pragma unroll
        for (int mf = 0; mf < 2; ++mf) {
            const int row = brow + wm + mf * 16 + g;
            if (row < a.M)
                *(float2*)(a.C + (size_t)row * a.N + col) =
                    make_float2(acc[mf][nf][0] + b0v, acc[mf][nf][1] + b1v);
            if (row + 8 < a.M)
                *(float2*)(a.C + (size_t)(row + 8) * a.N + col) =
                    make_float2(acc[mf][nf][2] + b0v, acc[mf][nf][3] + b1v);
        }
    }
}

// ---------------- CSR build (once per launch) --------------------------------
__global__ void zero_int_kernel(int* __restrict__ p, int n) {
    int i = blockIdx.x * 256 + threadIdx.x;
    if (i < n) p[i] = 0;
}

__global__ void hist_kernel(const int* __restrict__ esrc, const int* __restrict__ edst,
                            int* __restrict__ cntC, int* __restrict__ cntL, int E) {
    int e = blockIdx.x * 256 + threadIdx.x;
    if (e >= E) return;
    atomicAdd(&cntC[edst[e]], 1);
    atomicAdd(&cntL[esrc[e]], 1);
}

__global__ __launch_bounds__(1024) void scan_kernel(int* __restrict__ cnt,
                                                    int* __restrict__ cur, int n) {
    __shared__ int ts[1024];
    const int t = threadIdx.x;
    const int chunk = (n + 1023) / 1024;
    const int beg = t * chunk;
    const int end = min(beg + chunk, n);
    int s = 0;
    for (int i = beg; i < end; ++i) s += cnt[i];
    ts[t] = s;
    __syncthreads();
    for (int off = 1; off < 1024; off <<= 1) {
        int v = (t >= off) ? ts[t - off] : 0;
        __syncthreads();
        ts[t] += v;
        __syncthreads();
    }
    int run = (t == 0) ? 0 : ts[t - 1];
    for (int i = beg; i < end; ++i) {
        int cv = cnt[i];
        cnt[i] = run;
        cur[i] = run;
        run += cv;
    }
    if (beg < n && end == n) cnt[n] = run;
}

__global__ void place_kernel(const int* __restrict__ esrc, const int* __restrict__ edst,
                             int* __restrict__ curC, int* __restrict__ curL,
                             int* __restrict__ srcC, int* __restrict__ srcL, int E) {
    int e = blockIdx.x * 256 + threadIdx.x;
    if (e >= E) return;
    int s = esrc[e], d = edst[e];
    int pC = atomicAdd(&curC[d], 1);
    srcC[pC] = s;
    int pL = atomicAdd(&curL[s], 1);
    srcL[pL] = d;
}

// ---------------- segment sum + bf16 split (replaces zero+scatter+cvt) ------
__global__ void segsum_kernel(const float* __restrict__ rows,
                              const int* __restrict__ rowptr,
                              const int* __restrict__ srcidx,
                              uint32_t* __restrict__ hi, uint32_t* __restrict__ lo,
                              int M) {
    int seg = blockIdx.x * 8 + (threadIdx.x >> 5);
    if (seg >= M) return;
    const int lane = threadIdx.x & 31;
    const int beg = rowptr[seg], end = rowptr[seg + 1];
    float4 v = make_float4(0.f, 0.f, 0.f, 0.f);
    for (int j = beg; j < end; ++j) {
        int s = srcidx[j];
        float4 u = *(const float4*)(rows + (size_t)s * D_ + lane * 4);
        v.x += u.x; v.y += u.y; v.z += u.z; v.w += u.w;
    }
    uint32_t h0, l0, h1, l1;
    cvt2(v.x, v.y, h0, l0);
    cvt2(v.z, v.w, h1, l1);
    *(uint2*)(hi + (size_t)seg * 64 + lane * 2) = make_uint2(h0, h1);
    *(uint2*)(lo + (size_t)seg * 64 + lane * 2) = make_uint2(l0, l1);
}

// ---------------- elementwise ----------------------------------------------
__device__ __forceinline__ float sigf(float x) {
    return __fdividef(1.f, 1.f + __expf(-x));
}
__device__ __forceinline__ float tanhfast(float x) {
    return __fdividef(2.f, 1.f + __expf(-2.f * x)) - 1.f;
}

__global__ void lstm_kernel(const float* __restrict__ gates,
                            float* __restrict__ h, float* __restrict__ c,
                            uint32_t* __restrict__ hhi, uint32_t* __restrict__ hlo,
                            int M) {
    size_t idx = (size_t)blockIdx.x * blockDim.x + threadIdx.x;
    if (idx >= (size_t)M * 32) return;
    size_t r = idx >> 5;
    int q = (int)(idx & 31) * 4;
    const float* gb = gates + r * 512;
    float4 gi = *(const float4*)(gb + q);
    float4 gf = *(const float4*)(gb + 128 + q);
    float4 gg = *(const float4*)(gb + 256 + q);
    float4 go = *(const float4*)(gb + 384 + q);
    float4 cc = *(const float4*)(c + r * D_ + q);
    float4 c2, hh;
    c2.x = sigf(gf.x) * cc.x + sigf(gi.x) * tanhfast(gg.x); hh.x = sigf(go.x) * tanhfast(c2.x);
    c2.y = sigf(gf.y) * cc.y + sigf(gi.y) * tanhfast(gg.y); hh.y = sigf(go.y) * tanhfast(c2.y);
    c2.z = sigf(gf.z) * cc.z + sigf(gi.z) * tanhfast(gg.z); hh.z = sigf(go.z) * tanhfast(c2.z);
    c2.w = sigf(gf.w) * cc.w + sigf(gi.w) * tanhfast(gg.w); hh.w = sigf(go.w) * tanhfast(c2.w);
    *(float4*)(c + r * D_ + q) = c2;
    *(float4*)(h + r * D_ + q) = hh;
    uint32_t h0, l0, h1, l1;
    cvt2(hh.x, hh.y, h0, l0);
    cvt2(hh.z, hh.w, h1, l1);
    *(uint2*)(hhi + r * 64 + (q >> 1)) = make_uint2(h0, h1);
    *(uint2*)(hlo + r * 64 + (q >> 1)) = make_uint2(l0, l1);
}

__global__ void init_kernel(const float* __restrict__ lw, const float* __restrict__ lb,
                            const float* __restrict__ cw, const float* __restrict__ cb,
                            float* __restrict__ h,
                            uint32_t* __restrict__ hhi, uint32_t* __restrict__ hlo) {
    int tid = threadIdx.x;           // 0..63
    size_t row = blockIdx.x;
    int d0 = tid * 2;
    float v0, v1;
    if (row < V2_) { v0 = lw[d0] + lb[d0]; v1 = lw[d0 + 1] + lb[d0 + 1]; }
    else           { v0 = cw[d0] + cb[d0]; v1 = cw[d0 + 1] + cb[d0 + 1]; }
    h[row * D_ + d0] = v0;
    h[row * D_ + d0 + 1] = v1;
    uint32_t hv, lv;
    cvt2(v0, v1, hv, lv);
    hhi[row * 64 + tid] = hv;
    hlo[row * 64 + tid] = lv;
}

__global__ void cvt_pairs(const float2* __restrict__ src,
                          uint32_t* __restrict__ hi, uint32_t* __restrict__ lo, size_t n) {
    size_t i = (size_t)blockIdx.x * blockDim.x + threadIdx.x;
    if (i >= n) return;
    float2 v = src[i];
    uint32_t hv, lv;
    cvt2(v.x, v.y, hv, lv);
    hi[i] = hv; lo[i] = lv;
}

__global__ void zero_kernel(float4* __restrict__ p, size_t n4) {
    size_t i = (size_t)blockIdx.x * blockDim.x + threadIdx.x;
    if (i < n4) p[i] = make_float4(0.f, 0.f, 0.f, 0.f);
}

__global__ void copy_kernel(const float4* __restrict__ src, float4* __restrict__ dst, size_t n4) {
    size_t i = (size_t)blockIdx.x * blockDim.x + threadIdx.x;
    if (i < n4) dst[i] = src[i];
}

// ---------------- host -------------------------------------------------------
extern "C" void kernel_launch(void* const* d_in, const int* in_sizes, int n_in,
                              void* d_out, int out_size) {
    const float* L_init_w = (const float*)d_in[0];
    const float* L_init_b = (const float*)d_in[1];
    const float* C_init_w = (const float*)d_in[2];
    const float* C_init_b = (const float*)d_in[3];
    const float* Lmsg_w   = (const float*)d_in[4];
    const float* Lmsg_b   = (const float*)d_in[5];
    const float* Cmsg_w   = (const float*)d_in[6];
    const float* Cmsg_b   = (const float*)d_in[7];
    const float* Cu_wih   = (const float*)d_in[8];
    const float* Cu_whh   = (const float*)d_in[9];
    const float* Cu_bih   = (const float*)d_in[10];
    const float* Cu_bhh   = (const float*)d_in[11];
    const float* Lu_wih   = (const float*)d_in[12];
    const float* Lu_whh   = (const float*)d_in[13];
    const float* Lu_bih   = (const float*)d_in[14];
    const float* Lu_bhh   = (const float*)d_in[15];
    const int*   esrc     = (const int*)d_in[16];
    const int*   edst     = (const int*)d_in[17];
    const int E = in_sizes[16];

    static int smem_set = 0;
    if (!smem_set) {
        cudaFuncSetAttribute(tc_gemm, cudaFuncAttributeMaxDynamicSharedMemorySize, SMEM_TC_BYTES);
        cudaFuncSetAttribute(mlp3_kernel, cudaFuncAttributeMaxDynamicSharedMemorySize, SMEM_FUSED);
        cudaFuncSetAttribute(gates2_kernel, cudaFuncAttributeMaxDynamicSharedMemorySize, SMEM_FUSED);
        smem_set = 1;
    }

    float *h, *c, *t0, *gates;
    uint32_t *hhi, *hlo, *mhi, *mlo, *whi, *wlo;
    int *cntC, *cntL, *curC, *curL, *srcC, *srcL;
    cudaGetSymbolAddress((void**)&h,     g_h);
    cudaGetSymbolAddress((void**)&c,     g_c);
    cudaGetSymbolAddress((void**)&t0,    g_t0);
    cudaGetSymbolAddress((void**)&gates, g_gates);
    cudaGetSymbolAddress((void**)&hhi,   g_hhi);
    cudaGetSymbolAddress((void**)&hlo,   g_hlo);
    cudaGetSymbolAddress((void**)&mhi,   g_mhi);
    cudaGetSymbolAddress((void**)&mlo,   g_mlo);
    cudaGetSymbolAddress((void**)&whi,   g_whi);
    cudaGetSymbolAddress((void**)&wlo,   g_wlo);
    cudaGetSymbolAddress((void**)&cntC,  g_cntC);
    cudaGetSymbolAddress((void**)&cntL,  g_cntL);
    cudaGetSymbolAddress((void**)&curC,  g_curC);
    cudaGetSymbolAddress((void**)&curL,  g_curL);
    cudaGetSymbolAddress((void**)&srcC,  g_srcC);
    cudaGetSymbolAddress((void**)&srcL,  g_srcL);

    // ---- pre-convert weights ----
    cvt_pairs<<<(24576 + 255) / 256, 256>>>((const float2*)Lmsg_w, whi + WO_LMSG, wlo + WO_LMSG, 24576);
    cvt_pairs<<<(24576 + 255) / 256, 256>>>((const float2*)Cmsg_w, whi + WO_CMSG, wlo + WO_CMSG, 24576);
    cvt_pairs<<<(32768 + 255) / 256, 256>>>((const float2*)Cu_wih, whi + WO_CWIH, wlo + WO_CWIH, 32768);
    cvt_pairs<<<(32768 + 255) / 256, 256>>>((const float2*)Cu_whh, whi + WO_CWHH, wlo + WO_CWHH, 32768);
    cvt_pairs<<<(65536 + 255) / 256, 256>>>((const float2*)Lu_wih, whi + WO_LWIH, wlo + WO_LWIH, 65536);
    cvt_pairs<<<(32768 + 255) / 256, 256>>>((const float2*)Lu_whh, whi + WO_LWHH, wlo + WO_LWHH, 32768);

    // ---- build CSR (both directions) ----
    zero_int_kernel<<<(NCL + 256) / 256, 256>>>(cntC, NCL + 1);
    zero_int_kernel<<<(V2_ + 256) / 256, 256>>>(cntL, V2_ + 1);
    hist_kernel<<<(E + 255) / 256, 256>>>(esrc, edst, cntC, cntL, E);
    scan_kernel<<<1, 1024>>>(cntC, curC, NCL);
    scan_kernel<<<1, 1024>>>(cntL, curL, V2_);
    place_kernel<<<(E + 255) / 256, 256>>>(esrc, edst, curC, curL, srcC, srcL, E);

    init_kernel<<<NTOTAL, 64>>>(L_init_w, L_init_b, C_init_w, C_init_b, h, hhi, hlo);
    zero_kernel<<<((size_t)NTOTAL * 32 + 255) / 256, 256>>>((float4*)c, (size_t)NTOTAL * 32);

    const int gv = (V2_ + 127) >> 7;    // 782
    const int gc = (NCL + 127) >> 7;    // 1563

    for (int r = 0; r < NROUNDS; ++r) {
        // ---- L-MLP fused -> t0 ----
        mlp3_kernel<<<gv, 512, SMEM_FUSED>>>(hhi, hlo, whi + WO_LMSG, wlo + WO_LMSG,
                                             Lmsg_b, t0, V2_);
        // ---- clause message segment-sum (+ bf16 split) ----
        segsum_kernel<<<(NCL + 7) / 8, 256>>>(t0, cntC, srcC, mhi, mlo, NCL);

        // ---- clause gates fused + LSTM ----
        gates2_kernel<<<gc, 512, SMEM_FUSED>>>(
            mhi, mlo, hhi + (size_t)V2_ * 64, hlo + (size_t)V2_ * 64,
            whi + WO_CWIH, wlo + WO_CWIH, whi + WO_CWHH, wlo + WO_CWHH,
            Cu_bih, Cu_bhh, gates, NCL);
        lstm_kernel<<<((size_t)NCL * 32 + 255) / 256, 256>>>(
            gates, h + (size_t)V2_ * D_, c + (size_t)V2_ * D_,
            hhi + (size_t)V2_ * 64, hlo + (size_t)V2_ * 64, NCL);

        // ---- C-MLP fused -> t0 ----
        mlp3_kernel<<<gc, 512, SMEM_FUSED>>>(hhi + (size_t)V2_ * 64, hlo + (size_t)V2_ * 64,
                                             whi + WO_CMSG, wlo + WO_CMSG,
                                             Cmsg_b, t0, NCL);
        // ---- literal message segment-sum ----
        segsum_kernel<<<(V2_ + 7) / 8, 256>>>(t0, cntL, srcL, mhi, mlo, V2_);

        // ---- literal gates (3-term) + LSTM ----
        TcArgs a = {};
        a.Ahi[0] = mhi; a.Alo[0] = mlo;
        a.Bhi[0] = whi + WO_LWIH; a.Blo[0] = wlo + WO_LWIH; a.ldb32[0] = 128; a.bko32[0] = 0;
        a.Ahi[1] = hhi; a.Alo[1] = hlo; a.negflip[1] = 1;
        a.Bhi[1] = whi + WO_LWIH; a.Blo[1] = wlo + WO_LWIH; a.ldb32[1] = 128; a.bko32[1] = 64;
        a.Ahi[2] = hhi; a.Alo[2] = hlo;
        a.Bhi[2] = whi + WO_LWHH; a.Blo[2] = wlo + WO_LWHH; a.ldb32[2] = 64;
        a.nTerms = 3; a.bias0 = Lu_bih; a.bias1 = Lu_bhh;
        a.C = gates; a.M = V2_; a.N = 512;
        dim3 grid(gv, 4);
        tc_gemm<<<grid, 512, SMEM_TC_BYTES>>>(a);
        lstm_kernel<<<((size_t)V2_ * 32 + 255) / 256, 256>>>(gates, h, c, hhi, hlo, V2_);
    }

    copy_kernel<<<((size_t)NTOTAL * 32 + 255) / 256, 256>>>(
        (const float4*)h, (float4*)d_out, (size_t)NTOTAL * 32);
}

// round 15
// speedup vs baseline: 2.2902x; 1.7265x over previous
#include <cuda_runtime.h>
#include <cuda_fp16.h>
#include <cstdint>

#define D_      128
#define NVARS   50000
#define V2_     100000
#define NCL     200000
#define NTOTAL  300000
#define NROUNDS 16
#define EDG     800000

// ---------------- persistent scratch ---------------------------------------
__device__ float g_h[(size_t)NTOTAL * D_];
__device__ float g_c[(size_t)NTOTAL * D_];
__device__ float g_t0[(size_t)NCL * D_];
__device__ float g_gates[(size_t)NCL * 4 * D_];

// fp16 mirrors (u32 = packed half2, 64 u32 per 128-float row)
__device__ uint32_t g_hh[(size_t)NTOTAL * 64];
__device__ uint32_t g_mm[(size_t)NCL * 64];
// weights (u32 = packed half2)
#define WO_LMSG  0
#define WO_CMSG  24576
#define WO_CWIH  49152
#define WO_CWHH  81920
#define WO_LWIH  114688
#define WO_LWHH  180224
#define W_TOTAL  212992
__device__ uint32_t g_wh[W_TOTAL];

// CSR edge structures (built once per launch)
__device__ int g_cntC[NCL + 1];
__device__ int g_cntL[V2_ + 1];
__device__ int g_curC[NCL];
__device__ int g_curL[V2_];
__device__ int g_srcC[EDG];
__device__ int g_srcL[EDG];

// ---------------- helpers ---------------------------------------------------
__device__ __forceinline__ uint32_t cvt2h(float x, float y) {
    __half2 hp = __floats2half2_rn(x, y);
    return *(uint32_t*)&hp;
}

__device__ __forceinline__ void mma_f16(float* d, const uint32_t* a, uint32_t b0, uint32_t b1) {
    asm volatile(
        "mma.sync.aligned.m16n8k16.row.col.f32.f16.f16.f32 "
        "{%0,%1,%2,%3}, {%4,%5,%6,%7}, {%8,%9}, {%0,%1,%2,%3};\n"
        : "+f"(d[0]), "+f"(d[1]), "+f"(d[2]), "+f"(d[3])
        : "r"(a[0]), "r"(a[1]), "r"(a[2]), "r"(a[3]), "r"(b0), "r"(b1));
}

__device__ __forceinline__ uint32_t smem_u32(const void* p) {
    uint32_t a;
    asm("{ .reg .u64 t; cvta.to.shared.u64 t, %1; cvt.u32.u64 %0, t; }" : "=r"(a) : "l"(p));
    return a;
}

__device__ __forceinline__ void cp16(uint32_t saddr, const void* g, bool pred) {
    int sz = pred ? 16 : 0;
    asm volatile("cp.async.cg.shared.global [%0], [%1], 16, %2;"
                 :: "r"(saddr), "l"(g), "r"(sz));
}
#define CP_COMMIT() asm volatile("cp.async.commit_group;" ::: "memory")

#define ASTR 36
#define SUB  4608                          // u32 per half-tile (128 x 32 u32 + pad)
#define SMEM_MLP ((size_t)(6 * SUB) * 4)   // 110592 B: A(2) + W0(2) + W1(2)
#define SMEM_G2  ((size_t)(6 * SUB) * 4)   // 110592 B: A0(2) + A1(2) + W(2)
#define STAGE_U32 (2 * SUB)
#define SMEM_TC  ((size_t)(2 * STAGE_U32) * 4)  // 73728 B

// fill one K=64 half-tile: 128 rows x 32 u32 (ld assumed 64 u32/row)
__device__ __forceinline__ void fill_half(uint32_t sb, uint32_t dst_u32,
                                          const uint32_t* __restrict__ gh,
                                          int rowbase, int kh, int M, int tid,
                                          int nflip) {
#pragma unroll
    for (int i = 0; i < 2; ++i) {
        int f = i * 512 + tid;
        int r = f >> 3, cch = f & 7;
        int gr = rowbase + r;
        bool p = gr < M;
        int src = p ? gr : 0;
        if (nflip) src = (src < NVARS) ? src + NVARS : src - NVARS;
        size_t go = (size_t)src * 64 + kh * 32 + cch * 4;
        uint32_t so = sb + (dst_u32 + (uint32_t)(r * ASTR + cch * 4)) * 4;
        cp16(so, gh + go, p);
    }
}

// acc += A(half) @ W(half)^T, 16 warps, 32x32 warp tiles
__device__ __forceinline__ void compute_half(const uint32_t* __restrict__ SA,
                                             const uint32_t* __restrict__ SW,
                                             float acc[2][4][4],
                                             int wm, int wn, int g, int t) {
#pragma unroll
    for (int ks = 0; ks < 4; ++ks) {
        const int c0 = ks * 8 + t;
        uint32_t ah[2][4];
#pragma unroll
        for (int mf = 0; mf < 2; ++mf) {
            const int r = wm + mf * 16 + g;
            const uint32_t* p = SA + r * ASTR + c0;
            ah[mf][0] = p[0]; ah[mf][1] = p[8 * ASTR];
            ah[mf][2] = p[4]; ah[mf][3] = p[8 * ASTR + 4];
        }
#pragma unroll
        for (int nf = 0; nf < 4; ++nf) {
            const int nr = wn + nf * 8 + g;
            const uint32_t* pb = SW + nr * ASTR + c0;
            uint32_t b0 = pb[0], b1 = pb[4];
#pragma unroll
            for (int mf = 0; mf < 2; ++mf)
                mma_f16(acc[mf][nf], ah[mf], b0, b1);
        }
    }
}

// ---------------- fused 3-layer MLP -----------------------------------------
__global__ __launch_bounds__(512, 2) void mlp3_kernel(
    const uint32_t* __restrict__ Ah,
    const uint32_t* __restrict__ Wh,
    const float* __restrict__ bias, float* __restrict__ Cout, int M) {
    extern __shared__ uint32_t sm[];
    const uint32_t sb = smem_u32(sm);
    const int tid  = threadIdx.x;
    const int wid  = tid >> 5;
    const int lane = tid & 31;
    const int g    = lane >> 2;
    const int t    = lane & 3;
    const int wm   = (wid >> 2) * 32;
    const int wn   = (wid & 3) * 32;
    const int brow = blockIdx.x << 7;

    fill_half(sb, 0,   Ah, brow, 0, M, tid, 0);
    fill_half(sb, SUB, Ah, brow, 1, M, tid, 0);
    CP_COMMIT();
    fill_half(sb, 2 * SUB, Wh, 0, 0, 128, tid, 0);
    fill_half(sb, 3 * SUB, Wh, 0, 1, 128, tid, 0);
    CP_COMMIT();

#pragma unroll
    for (int layer = 0; layer < 3; ++layer) {
        if (layer < 2) {
            const uint32_t wd = 2 * SUB + 2 * SUB * ((layer + 1) & 1);
            fill_half(sb, wd,       Wh + (layer + 1) * 8192, 0, 0, 128, tid, 0);
            fill_half(sb, wd + SUB, Wh + (layer + 1) * 8192, 0, 1, 128, tid, 0);
            CP_COMMIT();
            asm volatile("cp.async.wait_group 1;" ::: "memory");
        } else {
            asm volatile("cp.async.wait_group 0;" ::: "memory");
        }
        __syncthreads();

        const uint32_t* W = sm + 2 * SUB + 2 * SUB * (layer & 1);
        float acc[2][4][4];
#pragma unroll
        for (int mf = 0; mf < 2; ++mf)
#pragma unroll
            for (int nf = 0; nf < 4; ++nf)
#pragma unroll
                for (int k = 0; k < 4; ++k) acc[mf][nf][k] = 0.f;

        compute_half(sm,       W,       acc, wm, wn, g, t);
        compute_half(sm + SUB, W + SUB, acc, wm, wn, g, t);
        __syncthreads();

        const float* bl = bias + layer * 128;
        if (layer < 2) {
#pragma unroll
            for (int nf = 0; nf < 4; ++nf) {
                const int col = wn + nf * 8 + 2 * t;
                float b0v = bl[col], b1v = bl[col + 1];
                const int c32 = col >> 1;
                const uint32_t hbase = (c32 >> 5) * SUB;
                const int off = c32 & 31;
#pragma unroll
                for (int mf = 0; mf < 2; ++mf) {
                    const int r = wm + mf * 16 + g;
                    float x0 = fmaxf(acc[mf][nf][0] + b0v, 0.f);
                    float x1 = fmaxf(acc[mf][nf][1] + b1v, 0.f);
                    float x2 = fmaxf(acc[mf][nf][2] + b0v, 0.f);
                    float x3 = fmaxf(acc[mf][nf][3] + b1v, 0.f);
                    sm[hbase + r * ASTR + off]       = cvt2h(x0, x1);
                    sm[hbase + (r + 8) * ASTR + off] = cvt2h(x2, x3);
                }
            }
            __syncthreads();
        } else {
#pragma unroll
            for (int nf = 0; nf < 4; ++nf) {
                const int col = wn + nf * 8 + 2 * t;
                float b0v = bl[col], b1v = bl[col + 1];
#pragma unroll
                for (int mf = 0; mf < 2; ++mf) {
                    const int row = brow + wm + mf * 16 + g;
                    if (row < M)
                        *(float2*)(Cout + (size_t)row * 128 + col) =
                            make_float2(acc[mf][nf][0] + b0v, acc[mf][nf][1] + b1v);
                    if (row + 8 < M)
                        *(float2*)(Cout + (size_t)(row + 8) * 128 + col) =
                            make_float2(acc[mf][nf][2] + b0v, acc[mf][nf][3] + b1v);
                }
            }
        }
    }
}

// ---------------- fused 2-term gates GEMM ------------------------------------
__global__ __launch_bounds__(512, 2) void gates2_kernel(
    const uint32_t* __restrict__ A0h, const uint32_t* __restrict__ A1h,
    const uint32_t* __restrict__ Wihh, const uint32_t* __restrict__ Whhh,
    const float* __restrict__ bih, const float* __restrict__ bhh,
    float* __restrict__ gates, int M) {
    extern __shared__ uint32_t sm[];
    const uint32_t sb = smem_u32(sm);
    const int tid  = threadIdx.x;
    const int wid  = tid >> 5;
    const int lane = tid & 31;
    const int g    = lane >> 2;
    const int t    = lane & 3;
    const int wm   = (wid >> 2) * 32;
    const int wn   = (wid & 3) * 32;
    const int brow = blockIdx.x << 7;

    fill_half(sb, 0,       A0h, brow, 0, M, tid, 0);
    fill_half(sb, SUB,     A0h, brow, 1, M, tid, 0);
    fill_half(sb, 2 * SUB, A1h, brow, 0, M, tid, 0);
    fill_half(sb, 3 * SUB, A1h, brow, 1, M, tid, 0);
    CP_COMMIT();

    const uint32_t WB = 4 * SUB;
    for (int nt = 0; nt < 4; ++nt) {
        float acc[2][4][4];
#pragma unroll
        for (int mf = 0; mf < 2; ++mf)
#pragma unroll
            for (int nf = 0; nf < 4; ++nf)
#pragma unroll
                for (int k = 0; k < 4; ++k) acc[mf][nf][k] = 0.f;

#pragma unroll
        for (int term = 0; term < 2; ++term) {
            const uint32_t* wh = term ? Whhh : Wihh;
            fill_half(sb, WB,       wh, nt * 128, 0, 512, tid, 0);
            CP_COMMIT();
            fill_half(sb, WB + SUB, wh, nt * 128, 1, 512, tid, 0);
            CP_COMMIT();
            asm volatile("cp.async.wait_group 1;" ::: "memory");
            __syncthreads();
            compute_half(sm + term * 2 * SUB, sm + WB, acc, wm, wn, g, t);
            asm volatile("cp.async.wait_group 0;" ::: "memory");
            __syncthreads();
            compute_half(sm + term * 2 * SUB + SUB, sm + WB + SUB, acc, wm, wn, g, t);
            __syncthreads();
        }

#pragma unroll
        for (int nf = 0; nf < 4; ++nf) {
            const int col = nt * 128 + wn + nf * 8 + 2 * t;
            float b0v = bih[col] + bhh[col];
            float b1v = bih[col + 1] + bhh[col + 1];
#pragma unroll
            for (int mf = 0; mf < 2; ++mf) {
                const int row = brow + wm + mf * 16 + g;
                if (row < M)
                    *(float2*)(gates + (size_t)row * 512 + col) =
                        make_float2(acc[mf][nf][0] + b0v, acc[mf][nf][1] + b1v);
                if (row + 8 < M)
                    *(float2*)(gates + (size_t)(row + 8) * 512 + col) =
                        make_float2(acc[mf][nf][2] + b0v, acc[mf][nf][3] + b1v);
            }
        }
    }
}

// ---------------- generic GEMM (literal 3-term gates) ------------------------
struct TcArgs {
    const uint32_t* Ah[3];
    int negflip[3];
    const uint32_t* Bh[3];
    int ldb32[3], bko32[3];
    int nTerms;
    const float *bias0, *bias1;
    float* C;
    int M, N;
};

__device__ __forceinline__ void fill_stage(const TcArgs& a, int s, uint32_t sbase,
                                           int brow, int bcol, int tid) {
    const int term = s >> 1, kh = s & 1, b = s & 1;
    const uint32_t st = sbase + (uint32_t)b * (STAGE_U32 * 4);
    const uint32_t* gah = a.Ah[term];
    const int nflip = a.negflip[term];
#pragma unroll
    for (int i = 0; i < 2; ++i) {
        int f = i * 512 + tid;
        int r = f >> 3, cch = f & 7;
        int gr = brow + r;
        bool p = gr < a.M;
        int src = p ? gr : 0;
        if (nflip) src = (src < NVARS) ? src + NVARS : src - NVARS;
        size_t go = (size_t)src * 64 + kh * 32 + cch * 4;
        uint32_t so = st + (uint32_t)(r * ASTR + cch * 4) * 4;
        cp16(so, gah + go, p);
    }
    const uint32_t* gbh = a.Bh[term];
    const int ldb = a.ldb32[term], bko = a.bko32[term];
#pragma unroll
    for (int i = 0; i < 2; ++i) {
        int f = i * 512 + tid;
        int r = f >> 3, cch = f & 7;
        size_t go = (size_t)(bcol + r) * ldb + bko + kh * 32 + cch * 4;
        uint32_t so = st + (uint32_t)(SUB + r * ASTR + cch * 4) * 4;
        cp16(so, gbh + go, true);
    }
    CP_COMMIT();
}

__global__ __launch_bounds__(512) void tc_gemm(TcArgs a) {
    extern __shared__ uint32_t sm[];
    const uint32_t sbase = smem_u32(sm);
    const int tid  = threadIdx.x;
    const int wid  = tid >> 5;
    const int lane = tid & 31;
    const int g    = lane >> 2;
    const int t    = lane & 3;
    const int wm   = (wid >> 2) * 32;
    const int wn   = (wid & 3) * 32;
    const int brow = blockIdx.x << 7;
    const int bcol = blockIdx.y << 7;

    float acc[2][4][4];
#pragma unroll
    for (int mf = 0; mf < 2; ++mf)
#pragma unroll
        for (int nf = 0; nf < 4; ++nf)
#pragma unroll
            for (int k = 0; k < 4; ++k) acc[mf][nf][k] = 0.f;

    const int nst = a.nTerms * 2;
    fill_stage(a, 0, sbase, brow, bcol, tid);
    fill_stage(a, 1, sbase, brow, bcol, tid);

    for (int s = 0; s < nst; ++s) {
        const int b = s & 1;
        if (s + 1 < nst) asm volatile("cp.async.wait_group 1;" ::: "memory");
        else             asm volatile("cp.async.wait_group 0;" ::: "memory");
        __syncthreads();
        uint32_t* st = sm + b * STAGE_U32;
        compute_half(st, st + SUB, acc, wm, wn, g, t);
        __syncthreads();
        if (s + 2 < nst) fill_stage(a, s + 2, sbase, brow, bcol, tid);
    }

#pragma unroll
    for (int nf = 0; nf < 4; ++nf) {
        const int col = bcol + wn + nf * 8 + 2 * t;
        float b0v = a.bias0[col], b1v = a.bias0[col + 1];
        if (a.bias1) { b0v += a.bias1[col]; b1v += a.bias1[col + 1]; }
#pragma unroll
        for (int mf = 0; mf < 2; ++mf) {
            const int row = brow + wm + mf * 16 + g;
            if (row < a.M)
                *(float2*)(a.C + (size_t)row * a.N + col) =
                    make_float2(acc[mf][nf][0] + b0v, acc[mf][nf][1] + b1v);
            if (row + 8 < a.M)
                *(float2*)(a.C + (size_t)(row + 8) * a.N + col) =
                    make_float2(acc[mf][nf][2] + b0v, acc[mf][nf][3] + b1v);
        }
    }
}

// ---------------- CSR build ---------------------------------------------------
__global__ void zero_int_kernel(int* __restrict__ p, int n) {
    int i = blockIdx.x * 256 + threadIdx.x;
    if (i < n) p[i] = 0;
}

__global__ void hist_kernel(const int* __restrict__ esrc, const int* __restrict__ edst,
                            int* __restrict__ cntC, int* __restrict__ cntL, int E) {
    int e = blockIdx.x * 256 + threadIdx.x;
    if (e >= E) return;
    atomicAdd(&cntC[edst[e]], 1);
    atomicAdd(&cntL[esrc[e]], 1);
}

__global__ __launch_bounds__(1024) void scan_kernel(int* __restrict__ cnt,
                                                    int* __restrict__ cur, int n) {
    __shared__ int ts[1024];
    const int t = threadIdx.x;
    const int chunk = (n + 1023) / 1024;
    const int beg = t * chunk;
    const int end = min(beg + chunk, n);
    int s = 0;
    for (int i = beg; i < end; ++i) s += cnt[i];
    ts[t] = s;
    __syncthreads();
    for (int off = 1; off < 1024; off <<= 1) {
        int v = (t >= off) ? ts[t - off] : 0;
        __syncthreads();
        ts[t] += v;
        __syncthreads();
    }
    int run = (t == 0) ? 0 : ts[t - 1];
    for (int i = beg; i < end; ++i) {
        int cv = cnt[i];
        cnt[i] = run;
        cur[i] = run;
        run += cv;
    }
    if (beg < n && end == n) cnt[n] = run;
}

__global__ void place_kernel(const int* __restrict__ esrc, const int* __restrict__ edst,
                             int* __restrict__ curC, int* __restrict__ curL,
                             int* __restrict__ srcC, int* __restrict__ srcL, int E) {
    int e = blockIdx.x * 256 + threadIdx.x;
    if (e >= E) return;
    int s = esrc[e], d = edst[e];
    int pC = atomicAdd(&curC[d], 1);
    srcC[pC] = s;
    int pL = atomicAdd(&curL[s], 1);
    srcL[pL] = d;
}

// ---------------- segment sum + fp16 pack ------------------------------------
__global__ void segsum_kernel(const float* __restrict__ rows,
                              const int* __restrict__ rowptr,
                              const int* __restrict__ srcidx,
                              uint32_t* __restrict__ out, int M) {
    int seg = blockIdx.x * 8 + (threadIdx.x >> 5);
    if (seg >= M) return;
    const int lane = threadIdx.x & 31;
    const int beg = rowptr[seg], end = rowptr[seg + 1];
    float4 v = make_float4(0.f, 0.f, 0.f, 0.f);
    for (int j = beg; j < end; ++j) {
        int s = srcidx[j];
        float4 u = *(const float4*)(rows + (size_t)s * D_ + lane * 4);
        v.x += u.x; v.y += u.y; v.z += u.z; v.w += u.w;
    }
    *(uint2*)(out + (size_t)seg * 64 + lane * 2) =
        make_uint2(cvt2h(v.x, v.y), cvt2h(v.z, v.w));
}

// ---------------- elementwise ----------------------------------------------
__device__ __forceinline__ float sigf(float x) {
    return __fdividef(1.f, 1.f + __expf(-x));
}
__device__ __forceinline__ float tanhfast(float x) {
    return __fdividef(2.f, 1.f + __expf(-2.f * x)) - 1.f;
}

__global__ void lstm_kernel(const float* __restrict__ gates,
                            float* __restrict__ h, float* __restrict__ c,
                            uint32_t* __restrict__ hh, int M) {
    size_t idx = (size_t)blockIdx.x * blockDim.x + threadIdx.x;
    if (idx >= (size_t)M * 32) return;
    size_t r = idx >> 5;
    int q = (int)(idx & 31) * 4;
    const float* gb = gates + r * 512;
    float4 gi = *(const float4*)(gb + q);
    float4 gf = *(const float4*)(gb + 128 + q);
    float4 gg = *(const float4*)(gb + 256 + q);
    float4 go = *(const float4*)(gb + 384 + q);
    float4 cc = *(const float4*)(c + r * D_ + q);
    float4 c2, hv;
    c2.x = sigf(gf.x) * cc.x + sigf(gi.x) * tanhfast(gg.x); hv.x = sigf(go.x) * tanhfast(c2.x);
    c2.y = sigf(gf.y) * cc.y + sigf(gi.y) * tanhfast(gg.y); hv.y = sigf(go.y) * tanhfast(c2.y);
    c2.z = sigf(gf.z) * cc.z + sigf(gi.z) * tanhfast(gg.z); hv.z = sigf(go.z) * tanhfast(c2.z);
    c2.w = sigf(gf.w) * cc.w + sigf(gi.w) * tanhfast(gg.w); hv.w = sigf(go.w) * tanhfast(c2.w);
    *(float4*)(c + r * D_ + q) = c2;
    *(float4*)(h + r * D_ + q) = hv;
    *(uint2*)(hh + r * 64 + (q >> 1)) =
        make_uint2(cvt2h(hv.x, hv.y), cvt2h(hv.z, hv.w));
}

__global__ void init_kernel(const float* __restrict__ lw, const float* __restrict__ lb,
                            const float* __restrict__ cw, const float* __restrict__ cb,
                            float* __restrict__ h, uint32_t* __restrict__ hh) {
    int tid = threadIdx.x;           // 0..63
    size_t row = blockIdx.x;
    int d0 = tid * 2;
    float v0, v1;
    if (row < V2_) { v0 = lw[d0] + lb[d0]; v1 = lw[d0 + 1] + lb[d0 + 1]; }
    else           { v0 = cw[d0] + cb[d0]; v1 = cw[d0 + 1] + cb[d0 + 1]; }
    h[row * D_ + d0] = v0;
    h[row * D_ + d0 + 1] = v1;
    hh[row * 64 + tid] = cvt2h(v0, v1);
}

__global__ void cvt_pairs(const float2* __restrict__ src,
                          uint32_t* __restrict__ dst, size_t n) {
    size_t i = (size_t)blockIdx.x * blockDim.x + threadIdx.x;
    if (i >= n) return;
    float2 v = src[i];
    dst[i] = cvt2h(v.x, v.y);
}

__global__ void zero_kernel(float4* __restrict__ p, size_t n4) {
    size_t i = (size_t)blockIdx.x * blockDim.x + threadIdx.x;
    if (i < n4) p[i] = make_float4(0.f, 0.f, 0.f, 0.f);
}

__global__ void copy_kernel(const float4* __restrict__ src, float4* __restrict__ dst, size_t n4) {
    size_t i = (size_t)blockIdx.x * blockDim.x + threadIdx.x;
    if (i < n4) dst[i] = src[i];
}

// ---------------- host -------------------------------------------------------
extern "C" void kernel_launch(void* const* d_in, const int* in_sizes, int n_in,
                              void* d_out, int out_size) {
    const float* L_init_w = (const float*)d_in[0];
    const float* L_init_b = (const float*)d_in[1];
    const float* C_init_w = (const float*)d_in[2];
    const float* C_init_b = (const float*)d_in[3];
    const float* Lmsg_w   = (const float*)d_in[4];
    const float* Lmsg_b   = (const float*)d_in[5];
    const float* Cmsg_w   = (const float*)d_in[6];
    const float* Cmsg_b   = (const float*)d_in[7];
    const float* Cu_wih   = (const float*)d_in[8];
    const float* Cu_whh   = (const float*)d_in[9];
    const float* Cu_bih   = (const float*)d_in[10];
    const float* Cu_bhh   = (const float*)d_in[11];
    const float* Lu_wih   = (const float*)d_in[12];
    const float* Lu_whh   = (const float*)d_in[13];
    const float* Lu_bih   = (const float*)d_in[14];
    const float* Lu_bhh   = (const float*)d_in[15];
    const int*   esrc     = (const int*)d_in[16];
    const int*   edst     = (const int*)d_in[17];
    const int E = in_sizes[16];

    static int smem_set = 0;
    if (!smem_set) {
        cudaFuncSetAttribute(tc_gemm, cudaFuncAttributeMaxDynamicSharedMemorySize, SMEM_TC);
        cudaFuncSetAttribute(mlp3_kernel, cudaFuncAttributeMaxDynamicSharedMemorySize, SMEM_MLP);
        cudaFuncSetAttribute(gates2_kernel, cudaFuncAttributeMaxDynamicSharedMemorySize, SMEM_G2);
        smem_set = 1;
    }

    float *h, *c, *t0, *gates;
    uint32_t *hh, *mm, *wh;
    int *cntC, *cntL, *curC, *curL, *srcC, *srcL;
    cudaGetSymbolAddress((void**)&h,     g_h);
    cudaGetSymbolAddress((void**)&c,     g_c);
    cudaGetSymbolAddress((void**)&t0,    g_t0);
    cudaGetSymbolAddress((void**)&gates, g_gates);
    cudaGetSymbolAddress((void**)&hh,    g_hh);
    cudaGetSymbolAddress((void**)&mm,    g_mm);
    cudaGetSymbolAddress((void**)&wh,    g_wh);
    cudaGetSymbolAddress((void**)&cntC,  g_cntC);
    cudaGetSymbolAddress((void**)&cntL,  g_cntL);
    cudaGetSymbolAddress((void**)&curC,  g_curC);
    cudaGetSymbolAddress((void**)&curL,  g_curL);
    cudaGetSymbolAddress((void**)&srcC,  g_srcC);
    cudaGetSymbolAddress((void**)&srcL,  g_srcL);

    // ---- pre-convert weights to fp16 ----
    cvt_pairs<<<(24576 + 255) / 256, 256>>>((const float2*)Lmsg_w, wh + WO_LMSG, 24576);
    cvt_pairs<<<(24576 + 255) / 256, 256>>>((const float2*)Cmsg_w, wh + WO_CMSG, 24576);
    cvt_pairs<<<(32768 + 255) / 256, 256>>>((const float2*)Cu_wih, wh + WO_CWIH, 32768);
    cvt_pairs<<<(32768 + 255) / 256, 256>>>((const float2*)Cu_whh, wh + WO_CWHH, 32768);
    cvt_pairs<<<(65536 + 255) / 256, 256>>>((const float2*)Lu_wih, wh + WO_LWIH, 65536);
    cvt_pairs<<<(32768 + 255) / 256, 256>>>((const float2*)Lu_whh, wh + WO_LWHH, 32768);

    // ---- build CSR ----
    zero_int_kernel<<<(NCL + 256) / 256, 256>>>(cntC, NCL + 1);
    zero_int_kernel<<<(V2_ + 256) / 256, 256>>>(cntL, V2_ + 1);
    hist_kernel<<<(E + 255) / 256, 256>>>(esrc, edst, cntC, cntL, E);
    scan_kernel<<<1, 1024>>>(cntC, curC, NCL);
    scan_kernel<<<1, 1024>>>(cntL, curL, V2_);
    place_kernel<<<(E + 255) / 256, 256>>>(esrc, edst, curC, curL, srcC, srcL, E);

    init_kernel<<<NTOTAL, 64>>>(L_init_w, L_init_b, C_init_w, C_init_b, h, hh);
    zero_kernel<<<((size_t)NTOTAL * 32 + 255) / 256, 256>>>((float4*)c, (size_t)NTOTAL * 32);

    const int gv = (V2_ + 127) >> 7;    // 782
    const int gc = (NCL + 127) >> 7;    // 1563

    for (int r = 0; r < NROUNDS; ++r) {
        // ---- L-MLP fused -> t0 ----
        mlp3_kernel<<<gv, 512, SMEM_MLP>>>(hh, wh + WO_LMSG, Lmsg_b, t0, V2_);
        segsum_kernel<<<(NCL + 7) / 8, 256>>>(t0, cntC, srcC, mm, NCL);

        // ---- clause gates + LSTM ----
        gates2_kernel<<<gc, 512, SMEM_G2>>>(
            mm, hh + (size_t)V2_ * 64,
            wh + WO_CWIH, wh + WO_CWHH,
            Cu_bih, Cu_bhh, gates, NCL);
        lstm_kernel<<<((size_t)NCL * 32 + 255) / 256, 256>>>(
            gates, h + (size_t)V2_ * D_, c + (size_t)V2_ * D_,
            hh + (size_t)V2_ * 64, NCL);

        // ---- C-MLP fused -> t0 ----
        mlp3_kernel<<<gc, 512, SMEM_MLP>>>(hh + (size_t)V2_ * 64, wh + WO_CMSG,
                                           Cmsg_b, t0, NCL);
        segsum_kernel<<<(V2_ + 7) / 8, 256>>>(t0, cntL, srcL, mm, V2_);

        // ---- literal gates (3-term) + LSTM ----
        TcArgs a = {};
        a.Ah[0] = mm;
        a.Bh[0] = wh + WO_LWIH; a.ldb32[0] = 128; a.bko32[0] = 0;
        a.Ah[1] = hh; a.negflip[1] = 1;
        a.Bh[1] = wh + WO_LWIH; a.ldb32[1] = 128; a.bko32[1] = 64;
        a.Ah[2] = hh;
        a.Bh[2] = wh + WO_LWHH; a.ldb32[2] = 64;
        a.nTerms = 3; a.bias0 = Lu_bih; a.bias1 = Lu_bhh;
        a.C = gates; a.M = V2_; a.N = 512;
        dim3 grid(gv, 4);
        tc_gemm<<<grid, 512, SMEM_TC>>>(a);
        lstm_kernel<<<((size_t)V2_ * 32 + 255) / 256, 256>>>(gates, h, c, hh, V2_);
    }

    copy_kernel<<<((size_t)NTOTAL * 32 + 255) / 256, 256>>>(
        (const float4*)h, (float4*)d_out, (size_t)NTOTAL * 32);
}

// round 16
// speedup vs baseline: 2.6298x; 1.1483x over previous
#include <cuda_runtime.h>
#include <cuda_fp16.h>
#include <cstdint>

#define D_      128
#define NVARS   50000
#define V2_     100000
#define NCL     200000
#define NTOTAL  300000
#define NROUNDS 16
#define EDG     800000

// ---------------- persistent scratch ---------------------------------------
__device__ float g_h[(size_t)NTOTAL * D_];
__device__ float g_c[(size_t)NTOTAL * D_];
__device__ float g_t0[(size_t)NCL * D_];

// fp16 mirrors (u32 = packed half2, 64 u32 per 128-float row)
__device__ uint32_t g_chh[(size_t)NCL * 64];     // clause h (in-place safe)
__device__ uint32_t g_lhA[(size_t)V2_ * 64];     // literal h ping
__device__ uint32_t g_lhB[(size_t)V2_ * 64];     // literal h pong
__device__ uint32_t g_mm[(size_t)NCL * 64];      // messages
// weights (u32 = packed half2); gate matrices stored ROW-PERMUTED
#define WO_LMSG  0
#define WO_CMSG  24576
#define WO_CWIH  49152
#define WO_CWHH  81920
#define WO_LWIH  114688
#define WO_LWHH  180224
#define W_TOTAL  212992
__device__ uint32_t g_wh[W_TOTAL];
__device__ float g_pbC[512];
__device__ float g_pbL[512];

// CSR edge structures
__device__ int g_cntC[NCL + 1];
__device__ int g_cntL[V2_ + 1];
__device__ int g_curC[NCL];
__device__ int g_curL[V2_];
__device__ int g_srcC[EDG];
__device__ int g_srcL[EDG];

// ---------------- helpers ---------------------------------------------------
__device__ __forceinline__ uint32_t cvt2h(float x, float y) {
    __half2 hp = __floats2half2_rn(x, y);
    return *(uint32_t*)&hp;
}

__device__ __forceinline__ void mma_f16(float* d, const uint32_t* a, uint32_t b0, uint32_t b1) {
    asm volatile(
        "mma.sync.aligned.m16n8k16.row.col.f32.f16.f16.f32 "
        "{%0,%1,%2,%3}, {%4,%5,%6,%7}, {%8,%9}, {%0,%1,%2,%3};\n"
        : "+f"(d[0]), "+f"(d[1]), "+f"(d[2]), "+f"(d[3])
        : "r"(a[0]), "r"(a[1]), "r"(a[2]), "r"(a[3]), "r"(b0), "r"(b1));
}

__device__ __forceinline__ uint32_t smem_u32(const void* p) {
    uint32_t a;
    asm("{ .reg .u64 t; cvta.to.shared.u64 t, %1; cvt.u32.u64 %0, t; }" : "=r"(a) : "l"(p));
    return a;
}

__device__ __forceinline__ void cp16(uint32_t saddr, const void* g, bool pred) {
    int sz = pred ? 16 : 0;
    asm volatile("cp.async.cg.shared.global [%0], [%1], 16, %2;"
                 :: "r"(saddr), "l"(g), "r"(sz));
}
#define CP_COMMIT() asm volatile("cp.async.commit_group;" ::: "memory")

__device__ __forceinline__ float sigf(float x) {
    return __fdividef(1.f, 1.f + __expf(-x));
}
__device__ __forceinline__ float tanhfast(float x) {
    return __fdividef(2.f, 1.f + __expf(-2.f * x)) - 1.f;
}

#define ASTR 36
#define SUB  4608
#define SMEM_MLP ((size_t)(6 * SUB) * 4)   // 110592 B
#define SMEM_G2  ((size_t)(6 * SUB) * 4)
#define STAGE_U32 (2 * SUB)
#define SMEM_TC  ((size_t)(2 * STAGE_U32) * 4)  // 73728 B

__device__ __forceinline__ void fill_half(uint32_t sb, uint32_t dst_u32,
                                          const uint32_t* __restrict__ gh,
                                          int rowbase, int kh, int M, int tid,
                                          int nflip) {
#pragma unroll
    for (int i = 0; i < 2; ++i) {
        int f = i * 512 + tid;
        int r = f >> 3, cch = f & 7;
        int gr = rowbase + r;
        bool p = gr < M;
        int src = p ? gr : 0;
        if (nflip) src = (src < NVARS) ? src + NVARS : src - NVARS;
        size_t go = (size_t)src * 64 + kh * 32 + cch * 4;
        uint32_t so = sb + (dst_u32 + (uint32_t)(r * ASTR + cch * 4)) * 4;
        cp16(so, gh + go, p);
    }
}

__device__ __forceinline__ void compute_half(const uint32_t* __restrict__ SA,
                                             const uint32_t* __restrict__ SW,
                                             float acc[2][4][4],
                                             int wm, int wn, int g, int t) {
#pragma unroll
    for (int ks = 0; ks < 4; ++ks) {
        const int c0 = ks * 8 + t;
        uint32_t ah[2][4];
#pragma unroll
        for (int mf = 0; mf < 2; ++mf) {
            const int r = wm + mf * 16 + g;
            const uint32_t* p = SA + r * ASTR + c0;
            ah[mf][0] = p[0]; ah[mf][1] = p[8 * ASTR];
            ah[mf][2] = p[4]; ah[mf][3] = p[8 * ASTR + 4];
        }
#pragma unroll
        for (int nf = 0; nf < 4; ++nf) {
            const int nr = wn + nf * 8 + g;
            const uint32_t* pb = SW + nr * ASTR + c0;
            uint32_t b0 = pb[0], b1 = pb[4];
#pragma unroll
            for (int mf = 0; mf < 2; ++mf)
                mma_f16(acc[mf][nf], ah[mf], b0, b1);
        }
    }
}

// in-register LSTM epilogue (gate-interleaved permuted weights):
// acc[mf][nf=gate][k] = gate pre-bias for feature f0+(k&1), row (+8 if k>=2)
__device__ __forceinline__ void lstm_epi(
    float acc[2][4][4], const float* __restrict__ pb, int ntcol,
    int wm, int wn, int g, int t, int brow, int M,
    float* __restrict__ cbuf, float* __restrict__ hout,
    uint32_t* __restrict__ hhout) {
    float bg[4][2];
#pragma unroll
    for (int nf = 0; nf < 4; ++nf) {
        int col = ntcol + wn + nf * 8 + 2 * t;
        bg[nf][0] = pb[col]; bg[nf][1] = pb[col + 1];
    }
    const int f0 = (ntcol >> 2) + (wn >> 2) + 2 * t;   // nt*32 + wb*8 + 2t
#pragma unroll
    for (int mf = 0; mf < 2; ++mf) {
#pragma unroll
        for (int half = 0; half < 2; ++half) {
            const int row = brow + wm + mf * 16 + g + half * 8;
            if (row < M) {
                const int k0 = half * 2;
                float hres[2];
#pragma unroll
                for (int p = 0; p < 2; ++p) {
                    float iv = acc[mf][0][k0 + p] + bg[0][p];
                    float fv = acc[mf][1][k0 + p] + bg[1][p];
                    float gv = acc[mf][2][k0 + p] + bg[2][p];
                    float ov = acc[mf][3][k0 + p] + bg[3][p];
                    float cc = cbuf[(size_t)row * D_ + f0 + p];
                    float c2 = sigf(fv) * cc + sigf(iv) * tanhfast(gv);
                    float hv = sigf(ov) * tanhfast(c2);
                    cbuf[(size_t)row * D_ + f0 + p] = c2;
                    hout[(size_t)row * D_ + f0 + p] = hv;
                    hres[p] = hv;
                }
                hhout[(size_t)row * 64 + (f0 >> 1)] = cvt2h(hres[0], hres[1]);
            }
        }
    }
}

// ---------------- fused 3-layer MLP -----------------------------------------
__global__ __launch_bounds__(512, 2) void mlp3_kernel(
    const uint32_t* __restrict__ Ah,
    const uint32_t* __restrict__ Wh,
    const float* __restrict__ bias, float* __restrict__ Cout, int M) {
    extern __shared__ uint32_t sm[];
    const uint32_t sb = smem_u32(sm);
    const int tid  = threadIdx.x;
    const int wid  = tid >> 5;
    const int lane = tid & 31;
    const int g    = lane >> 2;
    const int t    = lane & 3;
    const int wm   = (wid >> 2) * 32;
    const int wn   = (wid & 3) * 32;
    const int brow = blockIdx.x << 7;

    fill_half(sb, 0,   Ah, brow, 0, M, tid, 0);
    fill_half(sb, SUB, Ah, brow, 1, M, tid, 0);
    CP_COMMIT();
    fill_half(sb, 2 * SUB, Wh, 0, 0, 128, tid, 0);
    fill_half(sb, 3 * SUB, Wh, 0, 1, 128, tid, 0);
    CP_COMMIT();

#pragma unroll
    for (int layer = 0; layer < 3; ++layer) {
        if (layer < 2) {
            const uint32_t wd = 2 * SUB + 2 * SUB * ((layer + 1) & 1);
            fill_half(sb, wd,       Wh + (layer + 1) * 8192, 0, 0, 128, tid, 0);
            fill_half(sb, wd + SUB, Wh + (layer + 1) * 8192, 0, 1, 128, tid, 0);
            CP_COMMIT();
            asm volatile("cp.async.wait_group 1;" ::: "memory");
        } else {
            asm volatile("cp.async.wait_group 0;" ::: "memory");
        }
        __syncthreads();

        const uint32_t* W = sm + 2 * SUB + 2 * SUB * (layer & 1);
        float acc[2][4][4];
#pragma unroll
        for (int mf = 0; mf < 2; ++mf)
#pragma unroll
            for (int nf = 0; nf < 4; ++nf)
#pragma unroll
                for (int k = 0; k < 4; ++k) acc[mf][nf][k] = 0.f;

        compute_half(sm,       W,       acc, wm, wn, g, t);
        compute_half(sm + SUB, W + SUB, acc, wm, wn, g, t);
        __syncthreads();

        const float* bl = bias + layer * 128;
        if (layer < 2) {
#pragma unroll
            for (int nf = 0; nf < 4; ++nf) {
                const int col = wn + nf * 8 + 2 * t;
                float b0v = bl[col], b1v = bl[col + 1];
                const int c32 = col >> 1;
                const uint32_t hbase = (c32 >> 5) * SUB;
                const int off = c32 & 31;
#pragma unroll
                for (int mf = 0; mf < 2; ++mf) {
                    const int r = wm + mf * 16 + g;
                    float x0 = fmaxf(acc[mf][nf][0] + b0v, 0.f);
                    float x1 = fmaxf(acc[mf][nf][1] + b1v, 0.f);
                    float x2 = fmaxf(acc[mf][nf][2] + b0v, 0.f);
                    float x3 = fmaxf(acc[mf][nf][3] + b1v, 0.f);
                    sm[hbase + r * ASTR + off]       = cvt2h(x0, x1);
                    sm[hbase + (r + 8) * ASTR + off] = cvt2h(x2, x3);
                }
            }
            __syncthreads();
        } else {
#pragma unroll
            for (int nf = 0; nf < 4; ++nf) {
                const int col = wn + nf * 8 + 2 * t;
                float b0v = bl[col], b1v = bl[col + 1];
#pragma unroll
                for (int mf = 0; mf < 2; ++mf) {
                    const int row = brow + wm + mf * 16 + g;
                    if (row < M)
                        *(float2*)(Cout + (size_t)row * 128 + col) =
                            make_float2(acc[mf][nf][0] + b0v, acc[mf][nf][1] + b1v);
                    if (row + 8 < M)
                        *(float2*)(Cout + (size_t)(row + 8) * 128 + col) =
                            make_float2(acc[mf][nf][2] + b0v, acc[mf][nf][3] + b1v);
                }
            }
        }
    }
}

// ---------------- fused 2-term gates GEMM + in-register LSTM -----------------
__global__ __launch_bounds__(512, 2) void gates2_kernel(
    const uint32_t* __restrict__ A0h, const uint32_t* __restrict__ A1h,
    const uint32_t* __restrict__ Wihh, const uint32_t* __restrict__ Whhh,
    const float* __restrict__ pb,
    float* __restrict__ cbuf, float* __restrict__ hout,
    uint32_t* __restrict__ hhout, int M) {
    extern __shared__ uint32_t sm[];
    const uint32_t sb = smem_u32(sm);
    const int tid  = threadIdx.x;
    const int wid  = tid >> 5;
    const int lane = tid & 31;
    const int g    = lane >> 2;
    const int t    = lane & 3;
    const int wm   = (wid >> 2) * 32;
    const int wn   = (wid & 3) * 32;
    const int brow = blockIdx.x << 7;

    fill_half(sb, 0,       A0h, brow, 0, M, tid, 0);
    fill_half(sb, SUB,     A0h, brow, 1, M, tid, 0);
    fill_half(sb, 2 * SUB, A1h, brow, 0, M, tid, 0);
    fill_half(sb, 3 * SUB, A1h, brow, 1, M, tid, 0);
    CP_COMMIT();

    const uint32_t WB = 4 * SUB;
    for (int nt = 0; nt < 4; ++nt) {
        float acc[2][4][4];
#pragma unroll
        for (int mf = 0; mf < 2; ++mf)
#pragma unroll
            for (int nf = 0; nf < 4; ++nf)
#pragma unroll
                for (int k = 0; k < 4; ++k) acc[mf][nf][k] = 0.f;

#pragma unroll
        for (int term = 0; term < 2; ++term) {
            const uint32_t* wh = term ? Whhh : Wihh;
            fill_half(sb, WB,       wh, nt * 128, 0, 512, tid, 0);
            CP_COMMIT();
            fill_half(sb, WB + SUB, wh, nt * 128, 1, 512, tid, 0);
            CP_COMMIT();
            asm volatile("cp.async.wait_group 1;" ::: "memory");
            __syncthreads();
            compute_half(sm + term * 2 * SUB, sm + WB, acc, wm, wn, g, t);
            asm volatile("cp.async.wait_group 0;" ::: "memory");
            __syncthreads();
            compute_half(sm + term * 2 * SUB + SUB, sm + WB + SUB, acc, wm, wn, g, t);
            __syncthreads();
        }
        lstm_epi(acc, pb, nt * 128, wm, wn, g, t, brow, M, cbuf, hout, hhout);
    }
}

// ---------------- 3-term gates GEMM + LSTM (literal path) --------------------
struct TcArgs {
    const uint32_t* Ah[3];
    int negflip[3];
    const uint32_t* Bh[3];
    int ldb32[3], bko32[3];
    const float* pb;
    float *cbuf, *hout;
    uint32_t* hhout;
    int M;
};

__device__ __forceinline__ void fill_stage(const TcArgs& a, int s, uint32_t sbase,
                                           int brow, int bcol, int tid) {
    const int term = s >> 1, kh = s & 1, b = s & 1;
    const uint32_t st = sbase + (uint32_t)b * (STAGE_U32 * 4);
    const uint32_t* gah = a.Ah[term];
    const int nflip = a.negflip[term];
#pragma unroll
    for (int i = 0; i < 2; ++i) {
        int f = i * 512 + tid;
        int r = f >> 3, cch = f & 7;
        int gr = brow + r;
        bool p = gr < a.M;
        int src = p ? gr : 0;
        if (nflip) src = (src < NVARS) ? src + NVARS : src - NVARS;
        size_t go = (size_t)src * 64 + kh * 32 + cch * 4;
        uint32_t so = st + (uint32_t)(r * ASTR + cch * 4) * 4;
        cp16(so, gah + go, p);
    }
    const uint32_t* gbh = a.Bh[term];
    const int ldb = a.ldb32[term], bko = a.bko32[term];
#pragma unroll
    for (int i = 0; i < 2; ++i) {
        int f = i * 512 + tid;
        int r = f >> 3, cch = f & 7;
        size_t go = (size_t)(bcol + r) * ldb + bko + kh * 32 + cch * 4;
        uint32_t so = st + (uint32_t)(SUB + r * ASTR + cch * 4) * 4;
        cp16(so, gbh + go, true);
    }
    CP_COMMIT();
}

__global__ __launch_bounds__(512) void gates3_kernel(TcArgs a) {
    extern __shared__ uint32_t sm[];
    const uint32_t sbase = smem_u32(sm);
    const int tid  = threadIdx.x;
    const int wid  = tid >> 5;
    const int lane = tid & 31;
    const int g    = lane >> 2;
    const int t    = lane & 3;
    const int wm   = (wid >> 2) * 32;
    const int wn   = (wid & 3) * 32;
    const int brow = blockIdx.x << 7;
    const int bcol = blockIdx.y << 7;

    float acc[2][4][4];
#pragma unroll
    for (int mf = 0; mf < 2; ++mf)
#pragma unroll
        for (int nf = 0; nf < 4; ++nf)
#pragma unroll
            for (int k = 0; k < 4; ++k) acc[mf][nf][k] = 0.f;

    const int nst = 6;
    fill_stage(a, 0, sbase, brow, bcol, tid);
    fill_stage(a, 1, sbase, brow, bcol, tid);

    for (int s = 0; s < nst; ++s) {
        const int b = s & 1;
        if (s + 1 < nst) asm volatile("cp.async.wait_group 1;" ::: "memory");
        else             asm volatile("cp.async.wait_group 0;" ::: "memory");
        __syncthreads();
        uint32_t* st = sm + b * STAGE_U32;
        compute_half(st, st + SUB, acc, wm, wn, g, t);
        __syncthreads();
        if (s + 2 < nst) fill_stage(a, s + 2, sbase, brow, bcol, tid);
    }

    lstm_epi(acc, a.pb, bcol, wm, wn, g, t, brow, a.M, a.cbuf, a.hout, a.hhout);
}

// ---------------- CSR build ---------------------------------------------------
__global__ void zero_int_kernel(int* __restrict__ p, int n) {
    int i = blockIdx.x * 256 + threadIdx.x;
    if (i < n) p[i] = 0;
}

__global__ void hist_kernel(const int* __restrict__ esrc, const int* __restrict__ edst,
                            int* __restrict__ cntC, int* __restrict__ cntL, int E) {
    int e = blockIdx.x * 256 + threadIdx.x;
    if (e >= E) return;
    atomicAdd(&cntC[edst[e]], 1);
    atomicAdd(&cntL[esrc[e]], 1);
}

__global__ __launch_bounds__(1024) void scan_kernel(int* __restrict__ cnt,
                                                    int* __restrict__ cur, int n) {
    __shared__ int ts[1024];
    const int t = threadIdx.x;
    const int chunk = (n + 1023) / 1024;
    const int beg = t * chunk;
    const int end = min(beg + chunk, n);
    int s = 0;
    for (int i = beg; i < end; ++i) s += cnt[i];
    ts[t] = s;
    __syncthreads();
    for (int off = 1; off < 1024; off <<= 1) {
        int v = (t >= off) ? ts[t - off] : 0;
        __syncthreads();
        ts[t] += v;
        __syncthreads();
    }
    int run = (t == 0) ? 0 : ts[t - 1];
    for (int i = beg; i < end; ++i) {
        int cv = cnt[i];
        cnt[i] = run;
        cur[i] = run;
        run += cv;
    }
    if (beg < n && end == n) cnt[n] = run;
}

__global__ void place_kernel(const int* __restrict__ esrc, const int* __restrict__ edst,
                             int* __restrict__ curC, int* __restrict__ curL,
                             int* __restrict__ srcC, int* __restrict__ srcL, int E) {
    int e = blockIdx.x * 256 + threadIdx.x;
    if (e >= E) return;
    int s = esrc[e], d = edst[e];
    int pC = atomicAdd(&curC[d], 1);
    srcC[pC] = s;
    int pL = atomicAdd(&curL[s], 1);
    srcL[pL] = d;
}

// ---------------- segment sum + fp16 pack ------------------------------------
__global__ void segsum_kernel(const float* __restrict__ rows,
                              const int* __restrict__ rowptr,
                              const int* __restrict__ srcidx,
                              uint32_t* __restrict__ out, int M) {
    int seg = blockIdx.x * 8 + (threadIdx.x >> 5);
    if (seg >= M) return;
    const int lane = threadIdx.x & 31;
    const int beg = rowptr[seg], end = rowptr[seg + 1];
    float4 v = make_float4(0.f, 0.f, 0.f, 0.f);
    for (int j = beg; j < end; ++j) {
        int s = srcidx[j];
        float4 u = *(const float4*)(rows + (size_t)s * D_ + lane * 4);
        v.x += u.x; v.y += u.y; v.z += u.z; v.w += u.w;
    }
    *(uint2*)(out + (size_t)seg * 64 + lane * 2) =
        make_uint2(cvt2h(v.x, v.y), cvt2h(v.z, v.w));
}

// ---------------- small kernels ----------------------------------------------
__global__ void init_kernel(const float* __restrict__ lw, const float* __restrict__ lb,
                            const float* __restrict__ cw, const float* __restrict__ cb,
                            float* __restrict__ h,
                            uint32_t* __restrict__ lh, uint32_t* __restrict__ chh) {
    int tid = threadIdx.x;           // 0..63
    size_t row = blockIdx.x;
    int d0 = tid * 2;
    float v0, v1;
    if (row < V2_) { v0 = lw[d0] + lb[d0]; v1 = lw[d0 + 1] + lb[d0 + 1]; }
    else           { v0 = cw[d0] + cb[d0]; v1 = cw[d0 + 1] + cb[d0 + 1]; }
    h[row * D_ + d0] = v0;
    h[row * D_ + d0 + 1] = v1;
    uint32_t pv = cvt2h(v0, v1);
    if (row < V2_) lh[row * 64 + tid] = pv;
    else           chh[(row - V2_) * 64 + tid] = pv;
}

__global__ void cvt_pairs(const float2* __restrict__ src,
                          uint32_t* __restrict__ dst, size_t n) {
    size_t i = (size_t)blockIdx.x * blockDim.x + threadIdx.x;
    if (i >= n) return;
    float2 v = src[i];
    dst[i] = cvt2h(v.x, v.y);
}

// gate-interleaved row permutation: new pr -> old row
__global__ void cvt_perm(const float2* __restrict__ src,
                         uint32_t* __restrict__ dst, int ld32) {
    int i = blockIdx.x * 256 + threadIdx.x;
    int n = 512 * ld32;
    if (i >= n) return;
    int pr = i / ld32, cc = i % ld32;
    int nt = pr >> 7, w = pr & 127;
    int wb = w >> 5, q = w & 31;
    int old = (q >> 3) * 128 + nt * 32 + wb * 8 + (q & 7);
    float2 v = src[(size_t)old * ld32 + cc];
    dst[i] = cvt2h(v.x, v.y);
}

__global__ void perm_bias(const float* __restrict__ b0, const float* __restrict__ b1,
                          float* __restrict__ out) {
    int pr = blockIdx.x * 256 + threadIdx.x;
    if (pr >= 512) return;
    int nt = pr >> 7, w = pr & 127;
    int wb = w >> 5, q = w & 31;
    int old = (q >> 3) * 128 + nt * 32 + wb * 8 + (q & 7);
    out[pr] = b0[old] + b1[old];
}

__global__ void zero_kernel(float4* __restrict__ p, size_t n4) {
    size_t i = (size_t)blockIdx.x * blockDim.x + threadIdx.x;
    if (i < n4) p[i] = make_float4(0.f, 0.f, 0.f, 0.f);
}

__global__ void copy_kernel(const float4* __restrict__ src, float4* __restrict__ dst, size_t n4) {
    size_t i = (size_t)blockIdx.x * blockDim.x + threadIdx.x;
    if (i < n4) dst[i] = src[i];
}

// ---------------- host -------------------------------------------------------
extern "C" void kernel_launch(void* const* d_in, const int* in_sizes, int n_in,
                              void* d_out, int out_size) {
    const float* L_init_w = (const float*)d_in[0];
    const float* L_init_b = (const float*)d_in[1];
    const float* C_init_w = (const float*)d_in[2];
    const float* C_init_b = (const float*)d_in[3];
    const float* Lmsg_w   = (const float*)d_in[4];
    const float* Lmsg_b   = (const float*)d_in[5];
    const float* Cmsg_w   = (const float*)d_in[6];
    const float* Cmsg_b   = (const float*)d_in[7];
    const float* Cu_wih   = (const float*)d_in[8];
    const float* Cu_whh   = (const float*)d_in[9];
    const float* Cu_bih   = (const float*)d_in[10];
    const float* Cu_bhh   = (const float*)d_in[11];
    const float* Lu_wih   = (const float*)d_in[12];
    const float* Lu_whh   = (const float*)d_in[13];
    const float* Lu_bih   = (const float*)d_in[14];
    const float* Lu_bhh   = (const float*)d_in[15];
    const int*   esrc     = (const int*)d_in[16];
    const int*   edst     = (const int*)d_in[17];
    const int E = in_sizes[16];

    static int smem_set = 0;
    if (!smem_set) {
        cudaFuncSetAttribute(gates3_kernel, cudaFuncAttributeMaxDynamicSharedMemorySize, SMEM_TC);
        cudaFuncSetAttribute(mlp3_kernel, cudaFuncAttributeMaxDynamicSharedMemorySize, SMEM_MLP);
        cudaFuncSetAttribute(gates2_kernel, cudaFuncAttributeMaxDynamicSharedMemorySize, SMEM_G2);
        smem_set = 1;
    }

    float *h, *c, *t0, *pbC, *pbL;
    uint32_t *chh, *lhA, *lhB, *mm, *wh;
    int *cntC, *cntL, *curC, *curL, *srcC, *srcL;
    cudaGetSymbolAddress((void**)&h,     g_h);
    cudaGetSymbolAddress((void**)&c,     g_c);
    cudaGetSymbolAddress((void**)&t0,    g_t0);
    cudaGetSymbolAddress((void**)&chh,   g_chh);
    cudaGetSymbolAddress((void**)&lhA,   g_lhA);
    cudaGetSymbolAddress((void**)&lhB,   g_lhB);
    cudaGetSymbolAddress((void**)&mm,    g_mm);
    cudaGetSymbolAddress((void**)&wh,    g_wh);
    cudaGetSymbolAddress((void**)&pbC,   g_pbC);
    cudaGetSymbolAddress((void**)&pbL,   g_pbL);
    cudaGetSymbolAddress((void**)&cntC,  g_cntC);
    cudaGetSymbolAddress((void**)&cntL,  g_cntL);
    cudaGetSymbolAddress((void**)&curC,  g_curC);
    cudaGetSymbolAddress((void**)&curL,  g_curL);
    cudaGetSymbolAddress((void**)&srcC,  g_srcC);
    cudaGetSymbolAddress((void**)&srcL,  g_srcL);

    // ---- pre-convert weights (gate matrices row-permuted) ----
    cvt_pairs<<<(24576 + 255) / 256, 256>>>((const float2*)Lmsg_w, wh + WO_LMSG, 24576);
    cvt_pairs<<<(24576 + 255) / 256, 256>>>((const float2*)Cmsg_w, wh + WO_CMSG, 24576);
    cvt_perm<<<128, 256>>>((const float2*)Cu_wih, wh + WO_CWIH, 64);
    cvt_perm<<<128, 256>>>((const float2*)Cu_whh, wh + WO_CWHH, 64);
    cvt_perm<<<256, 256>>>((const float2*)Lu_wih, wh + WO_LWIH, 128);
    cvt_perm<<<128, 256>>>((const float2*)Lu_whh, wh + WO_LWHH, 64);
    perm_bias<<<2, 256>>>(Cu_bih, Cu_bhh, pbC);
    perm_bias<<<2, 256>>>(Lu_bih, Lu_bhh, pbL);

    // ---- build CSR ----
    zero_int_kernel<<<(NCL + 256) / 256, 256>>>(cntC, NCL + 1);
    zero_int_kernel<<<(V2_ + 256) / 256, 256>>>(cntL, V2_ + 1);
    hist_kernel<<<(E + 255) / 256, 256>>>(esrc, edst, cntC, cntL, E);
    scan_kernel<<<1, 1024>>>(cntC, curC, NCL);
    scan_kernel<<<1, 1024>>>(cntL, curL, V2_);
    place_kernel<<<(E + 255) / 256, 256>>>(esrc, edst, curC, curL, srcC, srcL, E);

    init_kernel<<<NTOTAL, 64>>>(L_init_w, L_init_b, C_init_w, C_init_b, h, lhA, chh);
    zero_kernel<<<((size_t)NTOTAL * 32 + 255) / 256, 256>>>((float4*)c, (size_t)NTOTAL * 32);

    const int gv = (V2_ + 127) >> 7;    // 782
    const int gc = (NCL + 127) >> 7;    // 1563

    uint32_t* lh_cur = lhA;
    uint32_t* lh_nxt = lhB;

    for (int r = 0; r < NROUNDS; ++r) {
        // ---- L-MLP fused -> t0 ----
        mlp3_kernel<<<gv, 512, SMEM_MLP>>>(lh_cur, wh + WO_LMSG, Lmsg_b, t0, V2_);
        segsum_kernel<<<(NCL + 7) / 8, 256>>>(t0, cntC, srcC, mm, NCL);

        // ---- clause gates + fused LSTM (in-place clause hh update) ----
        gates2_kernel<<<gc, 512, SMEM_G2>>>(
            mm, chh, wh + WO_CWIH, wh + WO_CWHH, pbC,
            c + (size_t)V2_ * D_, h + (size_t)V2_ * D_, chh, NCL);

        // ---- C-MLP fused -> t0 ----
        mlp3_kernel<<<gc, 512, SMEM_MLP>>>(chh, wh + WO_CMSG, Cmsg_b, t0, NCL);
        segsum_kernel<<<(V2_ + 7) / 8, 256>>>(t0, cntL, srcL, mm, V2_);

        // ---- literal gates (3-term) + fused LSTM (ping-pong literal hh) ----
        TcArgs a = {};
        a.Ah[0] = mm;
        a.Bh[0] = wh + WO_LWIH; a.ldb32[0] = 128; a.bko32[0] = 0;
        a.Ah[1] = lh_cur; a.negflip[1] = 1;
        a.Bh[1] = wh + WO_LWIH; a.ldb32[1] = 128; a.bko32[1] = 64;
        a.Ah[2] = lh_cur;
        a.Bh[2] = wh + WO_LWHH; a.ldb32[2] = 64;
        a.pb = pbL;
        a.cbuf = c; a.hout = h; a.hhout = lh_nxt;
        a.M = V2_;
        dim3 grid(gv, 4);
        gates3_kernel<<<grid, 512, SMEM_TC>>>(a);

        uint32_t* tmp = lh_cur; lh_cur = lh_nxt; lh_nxt = tmp;
    }

    copy_kernel<<<((size_t)NTOTAL * 32 + 255) / 256, 256>>>(
        (const float4*)h, (float4*)d_out, (size_t)NTOTAL * 32);
}